// round 7
// baseline (speedup 1.0000x reference)
#include <cuda_runtime.h>
#include <math.h>
#include <stdint.h>

#ifndef M_PI
#define M_PI 3.14159265358979323846
#endif

#define BB   8
#define TT   4096
#define EE   1024
#define HH   16
#define DD   64
#define KTOP 24

// ===================== scratch (device globals) =====================
__device__ float  g_X  [BB * TT * EE];   // tf32-rounded, K-permuted hidden_states
__device__ float  g_Wt [EE * EE];        // transposed+rounded+K-permuted weight
__device__ float  g_Qt [BB * EE * TT];   // Q transposed: [b][e][t]
__device__ float  g_Kt [BB * EE * TT];   // K transposed: [b][e][t]
__device__ float  g_V  [BB * TT * EE];   // V normal:     [b][t][e]
__device__ float  g_agg[BB * TT * EE];   // aggregated (tf32-rounded, K-permuted)
__device__ float2 g_spec[BB * TT];
__device__ float2 g_tw [TT / 2];
__device__ float  g_mean[BB * TT];
__device__ float  g_topv[BB * KTOP];
__device__ int    g_topi[BB * KTOP];

// ===================== helpers =====================
__device__ __forceinline__ float tf32r(float x) {
    uint32_t u;
    asm("cvt.rna.tf32.f32 %0, %1;" : "=r"(u) : "f"(x));
    return __uint_as_float(u);
}
#define CP16(saddr, gptr) \
    asm volatile("cp.async.cg.shared.global [%0], [%1], 16;" :: "r"(saddr), "l"(gptr) : "memory")
#define CP_COMMIT() asm volatile("cp.async.commit_group;" ::: "memory")
#define CP_WAIT2()  asm volatile("cp.async.wait_group 2;" ::: "memory")

__device__ __forceinline__ uint32_t smem_u32(const void* p) {
    uint32_t a;
    asm("{ .reg .u64 t; cvta.to.shared.u64 t, %1; cvt.u32.u64 %0, t; }" : "=r"(a) : "l"(p));
    return a;
}

__device__ __forceinline__ void mma_tf32(float* d, uint32_t a0, uint32_t a1,
                                         uint32_t a2, uint32_t a3,
                                         uint32_t b0, uint32_t b1) {
    asm volatile(
        "mma.sync.aligned.m16n8k8.row.col.f32.tf32.tf32.f32 "
        "{%0,%1,%2,%3}, {%4,%5,%6,%7}, {%8,%9}, {%0,%1,%2,%3};"
        : "+f"(d[0]), "+f"(d[1]), "+f"(d[2]), "+f"(d[3])
        : "r"(a0), "r"(a1), "r"(a2), "r"(a3), "r"(b0), "r"(b1));
}

// ===================== init =====================
__global__ void init_kernel() {
    int i = blockIdx.x * blockDim.x + threadIdx.x;
    if (i < BB * TT) g_spec[i] = make_float2(0.f, 0.f);
    if (i < TT / 2) {
        double ang = -2.0 * M_PI * (double)i / (double)TT;
        double s, c;
        sincos(ang, &s, &c);
        g_tw[i] = make_float2((float)c, (float)s);
    }
}

// round to tf32 + K-permute within 8-groups: logical k -> slot 2*(k%4) + k/4
// Each thread handles 8 consecutive elements (one 8-group aligned).
__global__ void __launch_bounds__(256) round_x_kernel(const float* __restrict__ src) {
    size_t i8 = ((size_t)blockIdx.x * blockDim.x + threadIdx.x) * 8;
    float4 lo = *(const float4*)(src + i8);
    float4 hi = *(const float4*)(src + i8 + 4);
    float4 oA = make_float4(tf32r(lo.x), tf32r(hi.x), tf32r(lo.y), tf32r(hi.y));
    float4 oB = make_float4(tf32r(lo.z), tf32r(hi.z), tf32r(lo.w), tf32r(hi.w));
    *(float4*)(g_X + i8)     = oA;
    *(float4*)(g_X + i8 + 4) = oB;
}

// Wt[n][perm(k)] = round_tf32(W[k][n])
__global__ void __launch_bounds__(256) transpose_round_kernel(const float* __restrict__ W) {
    __shared__ float ts[32][33];
    int x  = blockIdx.x * 32 + threadIdx.x;   // n
    int y0 = blockIdx.y * 32;                 // k block
    for (int i = threadIdx.y; i < 32; i += 8)
        ts[i][threadIdx.x] = W[(size_t)(y0 + i) * EE + x];
    __syncthreads();
    int tx   = threadIdx.x;
    int txp  = (tx & 24) | ((tx & 3) << 1) | ((tx >> 2) & 1);   // permuted within 8
    int xo   = y0 + txp;                     // permuted k out
    int yo   = blockIdx.x * 32;              // n out
    for (int i = threadIdx.y; i < 32; i += 8)
        g_Wt[(size_t)(yo + i) * EE + xo] = tf32r(ts[tx][i]);
}

// ===================== tf32 mma.sync GEMM =====================
// C[M=32768, N=1024] = A[M,K=1024] * Bt[N,K]^T + bias   (A, Bt K-permuted)
// CTA 128x256, warp 64x64 (2x4 warps), K staged 32, 4-stage cp.async.
#define BM 128
#define BN 256
#define BK 32
#define NSTG 4
#define A_STRIDE 36
#define B_STRIDE 36
#define A_FLOATS (BM * A_STRIDE)           // 4608
#define B_FLOATS (BN * B_STRIDE)           // 9216
#define STG_FLOATS (A_FLOATS + B_FLOATS)   // 13824
#define GEMM_SMEM (NSTG * STG_FLOATS * 4)  // 221184 B

__global__ void __launch_bounds__(256, 1)
tf32_gemm_kernel(const float* __restrict__ A, const float* __restrict__ Bt,
                 const float* __restrict__ bias, float* __restrict__ C, int outmode)
{
    extern __shared__ float smem[];
    const int tid  = threadIdx.x;
    const int wid  = tid >> 5;
    const int lane = tid & 31;
    const int g    = lane >> 2;     // 0..7
    const int t4   = lane & 3;      // 0..3
    const int m0   = blockIdx.y * BM;
    const int n0   = blockIdx.x * BN;
    const int wm   = (wid >> 2) * 64;
    const int wn   = (wid & 3) * 64;

    const float* gA = A  + (size_t)m0 * EE;
    const float* gB = Bt + (size_t)n0 * EE;

    const uint32_t sbase = smem_u32(smem);
    const int arow = tid >> 3;          // 0..31
    const int ac4  = (tid & 7) << 2;    // 0..28

    auto load_stage = [&](int kt) {
        const int st = kt & (NSTG - 1);
        const uint32_t sA = sbase + st * STG_FLOATS * 4;
        const uint32_t sB = sA + A_FLOATS * 4;
        const float* ga = gA + kt * BK;
        const float* gb = gB + kt * BK;
#pragma unroll
        for (int i = 0; i < 4; i++) {
            int r = arow + i * 32;
            CP16(sA + (r * A_STRIDE + ac4) * 4, ga + (size_t)r * EE + ac4);
        }
#pragma unroll
        for (int i = 0; i < 8; i++) {
            int r = arow + i * 32;
            CP16(sB + (r * B_STRIDE + ac4) * 4, gb + (size_t)r * EE + ac4);
        }
    };

    float acc[4][8][4];
#pragma unroll
    for (int mt = 0; mt < 4; mt++)
#pragma unroll
        for (int nt = 0; nt < 8; nt++)
#pragma unroll
            for (int i = 0; i < 4; i++) acc[mt][nt][i] = 0.f;

    load_stage(0); CP_COMMIT();
    load_stage(1); CP_COMMIT();
    load_stage(2); CP_COMMIT();

    const int KT = EE / BK;   // 32
    for (int kt = 0; kt < KT; kt++) {
        CP_WAIT2();
        __syncthreads();
        if (kt + NSTG - 1 < KT) load_stage(kt + NSTG - 1);
        CP_COMMIT();

        const float* As = smem + (kt & (NSTG - 1)) * STG_FLOATS;
        const float* Bs = As + A_FLOATS;
        const float* Ath = As + (wm + g) * A_STRIDE + 2 * t4;   // +kk per ks
        const float* Bth = Bs + (wn + g) * B_STRIDE + 2 * t4;

        // double-buffered fragments across ks steps
        uint2 Af[2][4][2];
        uint2 Bf[2][8];
#pragma unroll
        for (int mt = 0; mt < 4; mt++) {
            const float* ap = Ath + mt * 16 * A_STRIDE;
            Af[0][mt][0] = *(const uint2*)(ap);
            Af[0][mt][1] = *(const uint2*)(ap + 8 * A_STRIDE);
        }
#pragma unroll
        for (int nt = 0; nt < 8; nt++)
            Bf[0][nt] = *(const uint2*)(Bth + nt * 8 * B_STRIDE);

#pragma unroll
        for (int ks = 0; ks < 4; ks++) {
            const int cb = ks & 1;
            if (ks < 3) {
                const int kk = (ks + 1) * 8;
#pragma unroll
                for (int mt = 0; mt < 4; mt++) {
                    const float* ap = Ath + mt * 16 * A_STRIDE + kk;
                    Af[cb ^ 1][mt][0] = *(const uint2*)(ap);
                    Af[cb ^ 1][mt][1] = *(const uint2*)(ap + 8 * A_STRIDE);
                }
#pragma unroll
                for (int nt = 0; nt < 8; nt++)
                    Bf[cb ^ 1][nt] = *(const uint2*)(Bth + nt * 8 * B_STRIDE + kk);
            }
#pragma unroll
            for (int mt = 0; mt < 4; mt++)
#pragma unroll
                for (int nt = 0; nt < 8; nt++)
                    mma_tf32(acc[mt][nt],
                             Af[cb][mt][0].x, Af[cb][mt][1].x,
                             Af[cb][mt][0].y, Af[cb][mt][1].y,
                             Bf[cb][nt].x, Bf[cb][nt].y);
        }
    }

    // ---- epilogue ----
    if (outmode == 0) {
#pragma unroll
        for (int nt = 0; nt < 8; nt++) {
            const int n  = n0 + wn + nt * 8 + 2 * t4;
            const float b0 = __ldg(bias + n);
            const float b1 = __ldg(bias + n + 1);
#pragma unroll
            for (int mt = 0; mt < 4; mt++) {
                const int mrow = m0 + wm + mt * 16 + g;
                float2 v0 = make_float2(acc[mt][nt][0] + b0, acc[mt][nt][1] + b1);
                float2 v1 = make_float2(acc[mt][nt][2] + b0, acc[mt][nt][3] + b1);
                *(float2*)&C[(size_t)mrow * EE + n]       = v0;
                *(float2*)&C[(size_t)(mrow + 8) * EE + n] = v1;
            }
        }
    } else {
        // transposed per batch: C[((b*E + n) * T) + t]
        const int bbv   = m0 >> 12;
        const int tbase = (m0 & 4095) + wm;
#pragma unroll
        for (int nt = 0; nt < 8; nt++) {
            const int n  = n0 + wn + nt * 8 + 2 * t4;
            const float b0 = __ldg(bias + n);
            const float b1 = __ldg(bias + n + 1);
            float* c0 = C + ((size_t)(bbv * EE + n) << 12);
            float* c1 = C + ((size_t)(bbv * EE + n + 1) << 12);
#pragma unroll
            for (int mt = 0; mt < 4; mt++) {
                const int t = tbase + mt * 16 + g;
                c0[t]     = acc[mt][nt][0] + b0;
                c1[t]     = acc[mt][nt][1] + b1;
                c0[t + 8] = acc[mt][nt][2] + b0;
                c1[t + 8] = acc[mt][nt][3] + b1;
            }
        }
    }
}

// ===================== FFT autocorrelation path (fp32) =====================
__device__ __forceinline__ void fft4096(float2* s, int tid, int nthreads) {
    int lm = 0;
    for (int m = 1; m < 4096; m <<= 1, lm++) {
        for (int i = tid; i < 2048; i += nthreads) {
            int j  = i & (m - 1);
            int i1 = ((i >> lm) << (lm + 1)) | j;
            int i2 = i1 + m;
            float2 w = g_tw[j << (11 - lm)];
            float2 u = s[i1];
            float2 v = s[i2];
            float vr = v.x * w.x - v.y * w.y;
            float vi = v.x * w.y + v.y * w.x;
            s[i1] = make_float2(u.x + vr, u.y + vi);
            s[i2] = make_float2(u.x - vr, u.y - vi);
        }
        __syncthreads();
    }
}

__global__ void __launch_bounds__(512) corrfft_kernel() {
    __shared__ float2 s[4096];
    const int tid = threadIdx.x;
    const int b   = blockIdx.x >> 7;
    const int e0  = (blockIdx.x & 127) * 8;

    float2 psum[8];
#pragma unroll
    for (int r = 0; r < 8; r++) psum[r] = make_float2(0.f, 0.f);

    for (int c = 0; c < 8; c++) {
        const int ch = e0 + c;
        const float* q = g_Qt + ((size_t)(b * 1024 + ch)) * 4096;
        const float* k = g_Kt + ((size_t)(b * 1024 + ch)) * 4096;
        __syncthreads();
        for (int i = tid; i < 4096; i += 512) {
            int r = __brev(i) >> 20;
            s[r] = make_float2(q[i], k[i]);
        }
        __syncthreads();
        fft4096(s, tid, 512);
#pragma unroll
        for (int r = 0; r < 8; r++) {
            int f = tid + (r << 9);
            float2 A  = s[f];
            float2 Bc = s[(4096 - f) & 4095];
            float qr = 0.5f * (A.x + Bc.x);
            float qi = 0.5f * (A.y - Bc.y);
            float kr = 0.5f * (A.y + Bc.y);
            float ki = 0.5f * (Bc.x - A.x);
            psum[r].x += qr * kr + qi * ki;
            psum[r].y += qi * kr - qr * ki;
        }
    }

    float2* spec = g_spec + b * 4096;
#pragma unroll
    for (int r = 0; r < 8; r++) {
        int f = tid + (r << 9);
        atomicAdd(&spec[f].x, psum[r].x);
        atomicAdd(&spec[f].y, psum[r].y);
    }
}

__global__ void __launch_bounds__(512) ifft_kernel() {
    __shared__ float2 s[4096];
    const int b   = blockIdx.x;
    const int tid = threadIdx.x;
    for (int i = tid; i < 4096; i += 512) {
        int r = __brev(i) >> 20;
        float2 v = g_spec[b * 4096 + i];
        s[r] = make_float2(v.x, -v.y);
    }
    __syncthreads();
    fft4096(s, tid, 512);
    const float scale = 1.0f / ((float)TT * (float)EE);
    for (int i = tid; i < 4096; i += 512)
        g_mean[b * 4096 + i] = s[i].x * scale;
}

__global__ void __launch_bounds__(256) topk_kernel() {
    __shared__ float sv[4096];
    __shared__ float rv[256];
    __shared__ int   ri[256];
    const int b   = blockIdx.x;
    const int tid = threadIdx.x;
    for (int i = tid; i < 4096; i += 256) sv[i] = g_mean[b * 4096 + i];
    __syncthreads();
    for (int kk = 0; kk < KTOP; kk++) {
        float best = -3.4e38f;
        int   bi   = 0;
        for (int i = tid; i < 4096; i += 256) {
            float v = sv[i];
            if (v > best) { best = v; bi = i; }
        }
        rv[tid] = best; ri[tid] = bi;
        __syncthreads();
        for (int st = 128; st > 0; st >>= 1) {
            if (tid < st) {
                float ov = rv[tid + st]; int oi = ri[tid + st];
                if (ov > rv[tid] || (ov == rv[tid] && oi < ri[tid])) {
                    rv[tid] = ov; ri[tid] = oi;
                }
            }
            __syncthreads();
        }
        if (tid == 0) {
            g_topv[b * KTOP + kk] = rv[0];
            g_topi[b * KTOP + kk] = ri[0];
            sv[ri[0]] = -3.4e38f;
        }
        __syncthreads();
    }
}

// agg[b,t,perm(e)] = round_tf32( sum_k w[g,k] * V[b,(t+d[g,k])%T,e] ),  g=(e/64)%8
__global__ void __launch_bounds__(256) agg_kernel() {
    __shared__ float ws[8 * KTOP];
    __shared__ int   ds[8 * KTOP];
    const int tid = threadIdx.x;
    if (tid < 8 * KTOP) { ws[tid] = g_topv[tid]; ds[tid] = g_topi[tid]; }
    __syncthreads();

    const int bt = blockIdx.x;
    const int b  = bt >> 12;
    const int t  = bt & 4095;
    const int e4 = tid << 2;
    const int gg = (e4 >> 6) & 7;

    const float* Vb = g_V + (size_t)b * TT * EE;
    float4 acc = make_float4(0.f, 0.f, 0.f, 0.f);
#pragma unroll
    for (int kk = 0; kk < KTOP; kk++) {
        int   tk = (t + ds[gg * KTOP + kk]) & 4095;
        float w  = ws[gg * KTOP + kk];
        float4 v = *(const float4*)&Vb[(size_t)tk * EE + e4];
        acc.x += w * v.x; acc.y += w * v.y; acc.z += w * v.z; acc.w += w * v.w;
    }
    // permuted scatter within the 8-group: logical k -> slot 2*(k%4)+k/4
    float* out  = g_agg + (size_t)bt * EE + (e4 & ~7);
    const int o = (e4 & 4) ? 1 : 0;   // e%8 in {0..3} -> even slots, {4..7} -> odd
    out[o + 0] = tf32r(acc.x);
    out[o + 2] = tf32r(acc.y);
    out[o + 4] = tf32r(acc.z);
    out[o + 6] = tf32r(acc.w);
}

// ===================== launch =====================
extern "C" void kernel_launch(void* const* d_in, const int* in_sizes, int n_in,
                              void* d_out, int out_size) {
    (void)in_sizes; (void)n_in; (void)out_size;
    const float* hs = (const float*)d_in[0];
    const float* Wq = (const float*)d_in[1];
    const float* bq = (const float*)d_in[2];
    const float* Wk = (const float*)d_in[3];
    const float* bk = (const float*)d_in[4];
    const float* Wv = (const float*)d_in[5];
    const float* bv = (const float*)d_in[6];
    const float* Wo = (const float*)d_in[7];
    const float* bo = (const float*)d_in[8];
    float* out = (float*)d_out;

    cudaFuncSetAttribute(tf32_gemm_kernel,
                         cudaFuncAttributeMaxDynamicSharedMemorySize, GEMM_SMEM);

    void *pX, *pWt, *pQt, *pKt, *pV, *pAgg;
    cudaGetSymbolAddress(&pX,   g_X);
    cudaGetSymbolAddress(&pWt,  g_Wt);
    cudaGetSymbolAddress(&pQt,  g_Qt);
    cudaGetSymbolAddress(&pKt,  g_Kt);
    cudaGetSymbolAddress(&pV,   g_V);
    cudaGetSymbolAddress(&pAgg, g_agg);

    init_kernel<<<(BB * TT + 255) / 256, 256>>>();
    round_x_kernel<<<(BB * TT * EE / 8) / 256, 256>>>(hs);

    const dim3 tgrid(EE / 32, EE / 32);
    const dim3 tblk(32, 8);
    const dim3 ggrid(EE / BN, (BB * TT) / BM);

    transpose_round_kernel<<<tgrid, tblk>>>(Wq);
    tf32_gemm_kernel<<<ggrid, 256, GEMM_SMEM>>>((const float*)pX, (const float*)pWt, bq, (float*)pQt, 1);

    transpose_round_kernel<<<tgrid, tblk>>>(Wk);
    tf32_gemm_kernel<<<ggrid, 256, GEMM_SMEM>>>((const float*)pX, (const float*)pWt, bk, (float*)pKt, 1);

    transpose_round_kernel<<<tgrid, tblk>>>(Wv);
    tf32_gemm_kernel<<<ggrid, 256, GEMM_SMEM>>>((const float*)pX, (const float*)pWt, bv, (float*)pV, 0);

    corrfft_kernel<<<BB * 128, 512>>>();
    ifft_kernel<<<BB, 512>>>();
    topk_kernel<<<BB, 256>>>();
    agg_kernel<<<BB * TT, 256>>>();

    transpose_round_kernel<<<tgrid, tblk>>>(Wo);
    tf32_gemm_kernel<<<ggrid, 256, GEMM_SMEM>>>((const float*)pAgg, (const float*)pWt, bo, out, 0);
}

// round 8
// speedup vs baseline: 1.4129x; 1.4129x over previous
#include <cuda_runtime.h>
#include <cuda_fp16.h>
#include <math.h>
#include <stdint.h>

#ifndef M_PI
#define M_PI 3.14159265358979323846
#endif

#define BB   8
#define TT   4096
#define EE   1024
#define HH   16
#define DD   64
#define KTOP 24

// ===================== scratch (device globals) =====================
__device__ __align__(16) __half g_Xh  [BB * TT * EE];  // fp16 hidden_states
__device__ __align__(16) __half g_Wth [EE * EE];       // current transposed fp16 weight
__device__ __align__(16) __half g_aggh[BB * TT * EE];  // fp16 aggregated
__device__ float  g_Qt [BB * EE * TT];   // Q transposed: [b][e][t]  (fp32)
__device__ float  g_Kt [BB * EE * TT];   // K transposed: [b][e][t]  (fp32)
__device__ float  g_V  [BB * TT * EE];   // V normal:     [b][t][e]  (fp32)
__device__ float2 g_spec[BB * TT];
__device__ float2 g_tw [TT / 2];
__device__ float  g_mean[BB * TT];
__device__ float  g_topv[BB * KTOP];
__device__ int    g_topi[BB * KTOP];

// ===================== helpers =====================
#define CP16(saddr, gptr) \
    asm volatile("cp.async.cg.shared.global [%0], [%1], 16;" :: "r"(saddr), "l"(gptr) : "memory")
#define CP_COMMIT() asm volatile("cp.async.commit_group;" ::: "memory")
#define CP_WAIT1()  asm volatile("cp.async.wait_group 1;" ::: "memory")

__device__ __forceinline__ uint32_t smem_u32(const void* p) {
    uint32_t a;
    asm("{ .reg .u64 t; cvta.to.shared.u64 t, %1; cvt.u32.u64 %0, t; }" : "=r"(a) : "l"(p));
    return a;
}

__device__ __forceinline__ void mma_f16(float* d, const uint32_t* a, const uint32_t* b) {
    asm volatile(
        "mma.sync.aligned.m16n8k16.row.col.f32.f16.f16.f32 "
        "{%0,%1,%2,%3}, {%4,%5,%6,%7}, {%8,%9}, {%0,%1,%2,%3};"
        : "+f"(d[0]), "+f"(d[1]), "+f"(d[2]), "+f"(d[3])
        : "r"(a[0]), "r"(a[1]), "r"(a[2]), "r"(a[3]), "r"(b[0]), "r"(b[1]));
}

// ===================== init =====================
__global__ void init_kernel() {
    int i = blockIdx.x * blockDim.x + threadIdx.x;
    if (i < BB * TT) g_spec[i] = make_float2(0.f, 0.f);
    if (i < TT / 2) {
        double ang = -2.0 * M_PI * (double)i / (double)TT;
        double s, c;
        sincos(ang, &s, &c);
        g_tw[i] = make_float2((float)c, (float)s);
    }
}

// convert hidden_states to fp16
__global__ void __launch_bounds__(256) half_x_kernel(const float* __restrict__ src) {
    size_t i4 = ((size_t)blockIdx.x * blockDim.x + threadIdx.x) * 4;
    float4 v = *(const float4*)(src + i4);
    __half2* o = (__half2*)(g_Xh + i4);
    o[0] = __floats2half2_rn(v.x, v.y);
    o[1] = __floats2half2_rn(v.z, v.w);
}

// Wth[n][k] = half(W[k][n])
__global__ void __launch_bounds__(256) transpose_half_kernel(const float* __restrict__ W) {
    __shared__ float ts[32][33];
    int x  = blockIdx.x * 32 + threadIdx.x;   // n
    int y0 = blockIdx.y * 32;                 // k
    for (int i = threadIdx.y; i < 32; i += 8)
        ts[i][threadIdx.x] = W[(size_t)(y0 + i) * EE + x];
    __syncthreads();
    int xo = y0 + threadIdx.x;                // k out
    int yo = blockIdx.x * 32;                 // n out
    for (int i = threadIdx.y; i < 32; i += 8)
        g_Wth[(size_t)(yo + i) * EE + xo] = __float2half_rn(ts[threadIdx.x][i]);
}

// ===================== fp16 mma.sync GEMM =====================
// C[M=32768, N=1024] = A[M,K=1024] * Bt[N,K]^T + bias   (A, Bt fp16; C fp32)
// CTA 128x256, warp 64x64 (2x4 warps), K staged 32, 3-stage cp.async.
#define BM 128
#define BN 256
#define BK 32
#define NSTG 3
#define A_WST 20                       // 32-bit words per A row (16 data + 4 pad)
#define B_WST 20
#define A_WORDS (BM * A_WST)           // 2560
#define B_WORDS (BN * B_WST)           // 5120
#define STG_WORDS (A_WORDS + B_WORDS)  // 7680
#define GEMM_SMEM (NSTG * STG_WORDS * 4)   // 92160 B

__global__ void __launch_bounds__(256, 1)
hgemm_kernel(const __half* __restrict__ A, const __half* __restrict__ Bt,
             const float* __restrict__ bias, float* __restrict__ C, int outmode)
{
    extern __shared__ uint32_t smw[];
    const int tid  = threadIdx.x;
    const int wid  = tid >> 5;
    const int lane = tid & 31;
    const int g    = lane >> 2;     // 0..7
    const int t4   = lane & 3;      // 0..3
    const int m0   = blockIdx.y * BM;
    const int n0   = blockIdx.x * BN;
    const int wm   = (wid >> 2) * 64;
    const int wn   = (wid & 3) * 64;

    const __half* gA = A  + (size_t)m0 * EE;
    const __half* gB = Bt + (size_t)n0 * EE;

    const uint32_t sbase = smem_u32(smw);

    // load K-slice [kt*32, kt*32+32) halves of every row into stage buffer
    auto load_stage = [&](int kt) {
        const int st = kt % NSTG;
        const uint32_t sA = sbase + st * STG_WORDS * 4;
        const uint32_t sB = sA + A_WORDS * 4;
        const __half* ga = gA + kt * BK;
        const __half* gb = gB + kt * BK;
#pragma unroll
        for (int i = 0; i < 2; i++) {           // A: 128 rows x 4 chunks
            int q = tid + (i << 8);
            int r = q >> 2, c = q & 3;
            CP16(sA + (r * A_WST + c * 4) * 4, ga + (size_t)r * EE + c * 8);
        }
#pragma unroll
        for (int i = 0; i < 4; i++) {           // B: 256 rows x 4 chunks
            int q = tid + (i << 8);
            int r = q >> 2, c = q & 3;
            CP16(sB + (r * B_WST + c * 4) * 4, gb + (size_t)r * EE + c * 8);
        }
    };

    float acc[4][8][4];
#pragma unroll
    for (int mt = 0; mt < 4; mt++)
#pragma unroll
        for (int nt = 0; nt < 8; nt++)
#pragma unroll
            for (int i = 0; i < 4; i++) acc[mt][nt][i] = 0.f;

    load_stage(0); CP_COMMIT();
    load_stage(1); CP_COMMIT();

    const int KT = EE / BK;   // 32
    for (int kt = 0; kt < KT; kt++) {
        CP_WAIT1();
        __syncthreads();
        if (kt + 2 < KT) load_stage(kt + 2);
        CP_COMMIT();

        const uint32_t* As = smw + (kt % NSTG) * STG_WORDS;
        const uint32_t* Bs = As + A_WORDS;

#pragma unroll
        for (int ks = 0; ks < 2; ks++) {        // two k16 chunks per stage
            const int kw = ks * 8;              // word offset within row
            uint32_t af[4][4], bf[8][2];
#pragma unroll
            for (int mt = 0; mt < 4; mt++) {
                const uint32_t* ap = As + (wm + mt * 16 + g) * A_WST + kw + t4;
                af[mt][0] = ap[0];              // row g,   k lo
                af[mt][1] = ap[8 * A_WST];      // row g+8, k lo
                af[mt][2] = ap[4];              // row g,   k hi
                af[mt][3] = ap[8 * A_WST + 4];  // row g+8, k hi
            }
#pragma unroll
            for (int nt = 0; nt < 8; nt++) {
                const uint32_t* bp = Bs + (wn + nt * 8 + g) * B_WST + kw + t4;
                bf[nt][0] = bp[0];
                bf[nt][1] = bp[4];
            }
#pragma unroll
            for (int mt = 0; mt < 4; mt++)
#pragma unroll
                for (int nt = 0; nt < 8; nt++)
                    mma_f16(acc[mt][nt], af[mt], bf[nt]);
        }
        __syncthreads();
    }

    // ---- epilogue ----
    if (outmode == 0) {
#pragma unroll
        for (int nt = 0; nt < 8; nt++) {
            const int n  = n0 + wn + nt * 8 + 2 * t4;
            const float b0 = __ldg(bias + n);
            const float b1 = __ldg(bias + n + 1);
#pragma unroll
            for (int mt = 0; mt < 4; mt++) {
                const int mrow = m0 + wm + mt * 16 + g;
                float2 v0 = make_float2(acc[mt][nt][0] + b0, acc[mt][nt][1] + b1);
                float2 v1 = make_float2(acc[mt][nt][2] + b0, acc[mt][nt][3] + b1);
                *(float2*)&C[(size_t)mrow * EE + n]       = v0;
                *(float2*)&C[(size_t)(mrow + 8) * EE + n] = v1;
            }
        }
    } else {
        // transposed per batch: C[((b*E + n) * T) + t]
        const int bbv   = m0 >> 12;
        const int tbase = (m0 & 4095) + wm;
#pragma unroll
        for (int nt = 0; nt < 8; nt++) {
            const int n  = n0 + wn + nt * 8 + 2 * t4;
            const float b0 = __ldg(bias + n);
            const float b1 = __ldg(bias + n + 1);
            float* c0 = C + ((size_t)(bbv * EE + n) << 12);
            float* c1 = C + ((size_t)(bbv * EE + n + 1) << 12);
#pragma unroll
            for (int mt = 0; mt < 4; mt++) {
                const int t = tbase + mt * 16 + g;
                c0[t]     = acc[mt][nt][0] + b0;
                c1[t]     = acc[mt][nt][1] + b1;
                c0[t + 8] = acc[mt][nt][2] + b0;
                c1[t + 8] = acc[mt][nt][3] + b1;
            }
        }
    }
}

// ===================== FFT autocorrelation path (fp32) =====================
__device__ __forceinline__ void fft4096(float2* s, int tid, int nthreads) {
    int lm = 0;
    for (int m = 1; m < 4096; m <<= 1, lm++) {
        for (int i = tid; i < 2048; i += nthreads) {
            int j  = i & (m - 1);
            int i1 = ((i >> lm) << (lm + 1)) | j;
            int i2 = i1 + m;
            float2 w = g_tw[j << (11 - lm)];
            float2 u = s[i1];
            float2 v = s[i2];
            float vr = v.x * w.x - v.y * w.y;
            float vi = v.x * w.y + v.y * w.x;
            s[i1] = make_float2(u.x + vr, u.y + vi);
            s[i2] = make_float2(u.x - vr, u.y - vi);
        }
        __syncthreads();
    }
}

__global__ void __launch_bounds__(512) corrfft_kernel() {
    __shared__ float2 s[4096];
    const int tid = threadIdx.x;
    const int b   = blockIdx.x >> 7;
    const int e0  = (blockIdx.x & 127) * 8;

    float2 psum[8];
#pragma unroll
    for (int r = 0; r < 8; r++) psum[r] = make_float2(0.f, 0.f);

    for (int c = 0; c < 8; c++) {
        const int ch = e0 + c;
        const float* q = g_Qt + ((size_t)(b * 1024 + ch)) * 4096;
        const float* k = g_Kt + ((size_t)(b * 1024 + ch)) * 4096;
        __syncthreads();
        for (int i = tid; i < 4096; i += 512) {
            int r = __brev(i) >> 20;
            s[r] = make_float2(q[i], k[i]);
        }
        __syncthreads();
        fft4096(s, tid, 512);
#pragma unroll
        for (int r = 0; r < 8; r++) {
            int f = tid + (r << 9);
            float2 A  = s[f];
            float2 Bc = s[(4096 - f) & 4095];
            float qr = 0.5f * (A.x + Bc.x);
            float qi = 0.5f * (A.y - Bc.y);
            float kr = 0.5f * (A.y + Bc.y);
            float ki = 0.5f * (Bc.x - A.x);
            psum[r].x += qr * kr + qi * ki;
            psum[r].y += qi * kr - qr * ki;
        }
    }

    float2* spec = g_spec + b * 4096;
#pragma unroll
    for (int r = 0; r < 8; r++) {
        int f = tid + (r << 9);
        atomicAdd(&spec[f].x, psum[r].x);
        atomicAdd(&spec[f].y, psum[r].y);
    }
}

__global__ void __launch_bounds__(512) ifft_kernel() {
    __shared__ float2 s[4096];
    const int b   = blockIdx.x;
    const int tid = threadIdx.x;
    for (int i = tid; i < 4096; i += 512) {
        int r = __brev(i) >> 20;
        float2 v = g_spec[b * 4096 + i];
        s[r] = make_float2(v.x, -v.y);
    }
    __syncthreads();
    fft4096(s, tid, 512);
    const float scale = 1.0f / ((float)TT * (float)EE);
    for (int i = tid; i < 4096; i += 512)
        g_mean[b * 4096 + i] = s[i].x * scale;
}

__global__ void __launch_bounds__(256) topk_kernel() {
    __shared__ float sv[4096];
    __shared__ float rv[256];
    __shared__ int   ri[256];
    const int b   = blockIdx.x;
    const int tid = threadIdx.x;
    for (int i = tid; i < 4096; i += 256) sv[i] = g_mean[b * 4096 + i];
    __syncthreads();
    for (int kk = 0; kk < KTOP; kk++) {
        float best = -3.4e38f;
        int   bi   = 0;
        for (int i = tid; i < 4096; i += 256) {
            float v = sv[i];
            if (v > best) { best = v; bi = i; }
        }
        rv[tid] = best; ri[tid] = bi;
        __syncthreads();
        for (int st = 128; st > 0; st >>= 1) {
            if (tid < st) {
                float ov = rv[tid + st]; int oi = ri[tid + st];
                if (ov > rv[tid] || (ov == rv[tid] && oi < ri[tid])) {
                    rv[tid] = ov; ri[tid] = oi;
                }
            }
            __syncthreads();
        }
        if (tid == 0) {
            g_topv[b * KTOP + kk] = rv[0];
            g_topi[b * KTOP + kk] = ri[0];
            sv[ri[0]] = -3.4e38f;
        }
        __syncthreads();
    }
}

// agg[b,t,e] = sum_k w[g,k] * V[b,(t+d[g,k])%T,e],  g = (e/64) % 8; -> fp16
__global__ void __launch_bounds__(256) agg_kernel() {
    __shared__ float ws[8 * KTOP];
    __shared__ int   ds[8 * KTOP];
    const int tid = threadIdx.x;
    if (tid < 8 * KTOP) { ws[tid] = g_topv[tid]; ds[tid] = g_topi[tid]; }
    __syncthreads();

    const int bt = blockIdx.x;
    const int b  = bt >> 12;
    const int t  = bt & 4095;
    const int e4 = tid << 2;
    const int gg = (e4 >> 6) & 7;

    const float* Vb = g_V + (size_t)b * TT * EE;
    float4 acc = make_float4(0.f, 0.f, 0.f, 0.f);
#pragma unroll
    for (int kk = 0; kk < KTOP; kk++) {
        int   tk = (t + ds[gg * KTOP + kk]) & 4095;
        float w  = ws[gg * KTOP + kk];
        float4 v = *(const float4*)&Vb[(size_t)tk * EE + e4];
        acc.x += w * v.x; acc.y += w * v.y; acc.z += w * v.z; acc.w += w * v.w;
    }
    __half2* o = (__half2*)(g_aggh + (size_t)bt * EE + e4);
    o[0] = __floats2half2_rn(acc.x, acc.y);
    o[1] = __floats2half2_rn(acc.z, acc.w);
}

// ===================== launch =====================
extern "C" void kernel_launch(void* const* d_in, const int* in_sizes, int n_in,
                              void* d_out, int out_size) {
    (void)in_sizes; (void)n_in; (void)out_size;
    const float* hs = (const float*)d_in[0];
    const float* Wq = (const float*)d_in[1];
    const float* bq = (const float*)d_in[2];
    const float* Wk = (const float*)d_in[3];
    const float* bk = (const float*)d_in[4];
    const float* Wv = (const float*)d_in[5];
    const float* bv = (const float*)d_in[6];
    const float* Wo = (const float*)d_in[7];
    const float* bo = (const float*)d_in[8];
    float* out = (float*)d_out;

    cudaFuncSetAttribute(hgemm_kernel,
                         cudaFuncAttributeMaxDynamicSharedMemorySize, GEMM_SMEM);

    void *pXh, *pWth, *pQt, *pKt, *pV, *pAggh;
    cudaGetSymbolAddress(&pXh,   g_Xh);
    cudaGetSymbolAddress(&pWth,  g_Wth);
    cudaGetSymbolAddress(&pQt,   g_Qt);
    cudaGetSymbolAddress(&pKt,   g_Kt);
    cudaGetSymbolAddress(&pV,    g_V);
    cudaGetSymbolAddress(&pAggh, g_aggh);

    init_kernel<<<(BB * TT + 255) / 256, 256>>>();
    half_x_kernel<<<(BB * TT * EE / 4) / 256, 256>>>(hs);

    const dim3 tgrid(EE / 32, EE / 32);
    const dim3 tblk(32, 8);
    const dim3 ggrid(EE / BN, (BB * TT) / BM);

    transpose_half_kernel<<<tgrid, tblk>>>(Wq);
    hgemm_kernel<<<ggrid, 256, GEMM_SMEM>>>((const __half*)pXh, (const __half*)pWth, bq, (float*)pQt, 1);

    transpose_half_kernel<<<tgrid, tblk>>>(Wk);
    hgemm_kernel<<<ggrid, 256, GEMM_SMEM>>>((const __half*)pXh, (const __half*)pWth, bk, (float*)pKt, 1);

    transpose_half_kernel<<<tgrid, tblk>>>(Wv);
    hgemm_kernel<<<ggrid, 256, GEMM_SMEM>>>((const __half*)pXh, (const __half*)pWth, bv, (float*)pV, 0);

    corrfft_kernel<<<BB * 128, 512>>>();
    ifft_kernel<<<BB, 512>>>();
    topk_kernel<<<BB, 256>>>();
    agg_kernel<<<BB * TT, 256>>>();

    transpose_half_kernel<<<tgrid, tblk>>>(Wo);
    hgemm_kernel<<<ggrid, 256, GEMM_SMEM>>>((const __half*)pAggh, (const __half*)pWth, bo, out, 0);
}

// round 9
// speedup vs baseline: 1.8220x; 1.2896x over previous
#include <cuda_runtime.h>
#include <cuda_fp16.h>
#include <math.h>
#include <stdint.h>

#ifndef M_PI
#define M_PI 3.14159265358979323846
#endif

#define BB   8
#define TT   4096
#define EE   1024
#define HH   16
#define DD   64
#define KTOP 24

// ===================== scratch (device globals) =====================
__device__ __align__(16) __half g_Xh  [BB * TT * EE];  // fp16 hidden_states
__device__ __align__(16) __half g_Wth [EE * EE];       // current transposed fp16 weight
__device__ __align__(16) __half g_Vh  [BB * TT * EE];  // fp16 V
__device__ __align__(16) __half g_aggh[BB * TT * EE];  // fp16 aggregated
__device__ float  g_Qt [BB * EE * TT];   // Q transposed: [b][e][t]  (fp32)
__device__ float  g_Kt [BB * EE * TT];   // K transposed: [b][e][t]  (fp32)
__device__ float2 g_spec[BB * TT];
__device__ float2 g_tw [TT / 2];
__device__ float  g_mean[BB * TT];
__device__ float  g_topv[BB * KTOP];
__device__ int    g_topi[BB * KTOP];

// ===================== helpers =====================
#define CP16(saddr, gptr) \
    asm volatile("cp.async.cg.shared.global [%0], [%1], 16;" :: "r"(saddr), "l"(gptr) : "memory")
#define CP_COMMIT() asm volatile("cp.async.commit_group;" ::: "memory")
#define CP_WAIT1()  asm volatile("cp.async.wait_group 1;" ::: "memory")

__device__ __forceinline__ uint32_t smem_u32(const void* p) {
    uint32_t a;
    asm("{ .reg .u64 t; cvta.to.shared.u64 t, %1; cvt.u32.u64 %0, t; }" : "=r"(a) : "l"(p));
    return a;
}

__device__ __forceinline__ void mma_f16(float* d, const uint32_t* a, const uint32_t* b) {
    asm volatile(
        "mma.sync.aligned.m16n8k16.row.col.f32.f16.f16.f32 "
        "{%0,%1,%2,%3}, {%4,%5,%6,%7}, {%8,%9}, {%0,%1,%2,%3};"
        : "+f"(d[0]), "+f"(d[1]), "+f"(d[2]), "+f"(d[3])
        : "r"(a[0]), "r"(a[1]), "r"(a[2]), "r"(a[3]), "r"(b[0]), "r"(b[1]));
}

__device__ __forceinline__ float2 cmulf(float2 a, float2 b) {
    return make_float2(a.x * b.x - a.y * b.y, a.x * b.y + a.y * b.x);
}

// ===================== init =====================
__global__ void init_kernel() {
    int i = blockIdx.x * blockDim.x + threadIdx.x;
    if (i < BB * TT) g_spec[i] = make_float2(0.f, 0.f);
    if (i < TT / 2) {
        double ang = -2.0 * M_PI * (double)i / (double)TT;
        double s, c;
        sincos(ang, &s, &c);
        g_tw[i] = make_float2((float)c, (float)s);
    }
}

// convert hidden_states to fp16
__global__ void __launch_bounds__(256) half_x_kernel(const float* __restrict__ src) {
    size_t i4 = ((size_t)blockIdx.x * blockDim.x + threadIdx.x) * 4;
    float4 v = *(const float4*)(src + i4);
    __half2* o = (__half2*)(g_Xh + i4);
    o[0] = __floats2half2_rn(v.x, v.y);
    o[1] = __floats2half2_rn(v.z, v.w);
}

// Wth[n][k] = half(W[k][n])
__global__ void __launch_bounds__(256) transpose_half_kernel(const float* __restrict__ W) {
    __shared__ float ts[32][33];
    int x  = blockIdx.x * 32 + threadIdx.x;   // n
    int y0 = blockIdx.y * 32;                 // k
    for (int i = threadIdx.y; i < 32; i += 8)
        ts[i][threadIdx.x] = W[(size_t)(y0 + i) * EE + x];
    __syncthreads();
    int xo = y0 + threadIdx.x;                // k out
    int yo = blockIdx.x * 32;                 // n out
    for (int i = threadIdx.y; i < 32; i += 8)
        g_Wth[(size_t)(yo + i) * EE + xo] = __float2half_rn(ts[threadIdx.x][i]);
}

// ===================== fp16 mma.sync GEMM =====================
// C[M=32768, N=1024] = A[M,K=1024] * Bt[N,K]^T + bias   (A, Bt fp16)
// CTA 128x256, warp 64x64 (2x4 warps), K staged 64, 3-stage cp.async,
// single barrier per stage. outmode: 0 = fp32 C[m,n]; 1 = fp32 transposed
// per batch C[((b*E+n)*T)+t]; 2 = fp16 C[m,n].
#define BM 128
#define BN 256
#define BK 64
#define NSTG 3
#define A_WST 36                       // 32-bit words per A row (32 data + 4 pad)
#define B_WST 36
#define A_WORDS (BM * A_WST)           // 4608
#define B_WORDS (BN * B_WST)           // 9216
#define STG_WORDS (A_WORDS + B_WORDS)  // 13824
#define GEMM_SMEM (NSTG * STG_WORDS * 4)   // 165888 B

__global__ void __launch_bounds__(256, 1)
hgemm_kernel(const __half* __restrict__ A, const __half* __restrict__ Bt,
             const float* __restrict__ bias, float* __restrict__ C, int outmode)
{
    extern __shared__ uint32_t smw[];
    const int tid  = threadIdx.x;
    const int wid  = tid >> 5;
    const int lane = tid & 31;
    const int g    = lane >> 2;     // 0..7
    const int t4   = lane & 3;      // 0..3
    const int m0   = blockIdx.y * BM;
    const int n0   = blockIdx.x * BN;
    const int wm   = (wid >> 2) * 64;
    const int wn   = (wid & 3) * 64;

    const __half* gA = A  + (size_t)m0 * EE;
    const __half* gB = Bt + (size_t)n0 * EE;

    const uint32_t sbase = smem_u32(smw);

    // load K-slice [kt*64, kt*64+64) halves of every row into stage buffer
    auto load_stage = [&](int kt) {
        const int st = kt % NSTG;
        const uint32_t sA = sbase + st * STG_WORDS * 4;
        const uint32_t sB = sA + A_WORDS * 4;
        const __half* ga = gA + kt * BK;
        const __half* gb = gB + kt * BK;
#pragma unroll
        for (int i = 0; i < 4; i++) {           // A: 128 rows x 8 chunks
            int q = tid + (i << 8);
            int r = q >> 3, c = q & 7;
            CP16(sA + (r * A_WST + c * 4) * 4, ga + (size_t)r * EE + c * 8);
        }
#pragma unroll
        for (int i = 0; i < 8; i++) {           // B: 256 rows x 8 chunks
            int q = tid + (i << 8);
            int r = q >> 3, c = q & 7;
            CP16(sB + (r * B_WST + c * 4) * 4, gb + (size_t)r * EE + c * 8);
        }
    };

    float acc[4][8][4];
#pragma unroll
    for (int mt = 0; mt < 4; mt++)
#pragma unroll
        for (int nt = 0; nt < 8; nt++)
#pragma unroll
            for (int i = 0; i < 4; i++) acc[mt][nt][i] = 0.f;

    load_stage(0); CP_COMMIT();
    load_stage(1); CP_COMMIT();

    const int KT = EE / BK;   // 16
    for (int kt = 0; kt < KT; kt++) {
        CP_WAIT1();
        __syncthreads();      // stage kt visible to all; prior-stage readers done
        if (kt + 2 < KT) load_stage(kt + 2);
        CP_COMMIT();

        const uint32_t* As = smw + (kt % NSTG) * STG_WORDS;
        const uint32_t* Bs = As + A_WORDS;

#pragma unroll
        for (int ks = 0; ks < 4; ks++) {        // four k16 chunks per stage
            const int kw = ks * 8;              // word offset within row
            uint32_t af[4][4], bf[8][2];
#pragma unroll
            for (int mt = 0; mt < 4; mt++) {
                const uint32_t* ap = As + (wm + mt * 16 + g) * A_WST + kw + t4;
                af[mt][0] = ap[0];
                af[mt][1] = ap[8 * A_WST];
                af[mt][2] = ap[4];
                af[mt][3] = ap[8 * A_WST + 4];
            }
#pragma unroll
            for (int nt = 0; nt < 8; nt++) {
                const uint32_t* bp = Bs + (wn + nt * 8 + g) * B_WST + kw + t4;
                bf[nt][0] = bp[0];
                bf[nt][1] = bp[4];
            }
#pragma unroll
            for (int mt = 0; mt < 4; mt++)
#pragma unroll
                for (int nt = 0; nt < 8; nt++)
                    mma_f16(acc[mt][nt], af[mt], bf[nt]);
        }
    }

    // ---- epilogue ----
    if (outmode == 0) {
#pragma unroll
        for (int nt = 0; nt < 8; nt++) {
            const int n  = n0 + wn + nt * 8 + 2 * t4;
            const float b0 = __ldg(bias + n);
            const float b1 = __ldg(bias + n + 1);
#pragma unroll
            for (int mt = 0; mt < 4; mt++) {
                const int mrow = m0 + wm + mt * 16 + g;
                float2 v0 = make_float2(acc[mt][nt][0] + b0, acc[mt][nt][1] + b1);
                float2 v1 = make_float2(acc[mt][nt][2] + b0, acc[mt][nt][3] + b1);
                *(float2*)&C[(size_t)mrow * EE + n]       = v0;
                *(float2*)&C[(size_t)(mrow + 8) * EE + n] = v1;
            }
        }
    } else if (outmode == 1) {
        // transposed per batch: C[((b*E + n) * T) + t]
        const int bbv   = m0 >> 12;
        const int tbase = (m0 & 4095) + wm;
#pragma unroll
        for (int nt = 0; nt < 8; nt++) {
            const int n  = n0 + wn + nt * 8 + 2 * t4;
            const float b0 = __ldg(bias + n);
            const float b1 = __ldg(bias + n + 1);
            float* c0 = C + ((size_t)(bbv * EE + n) << 12);
            float* c1 = C + ((size_t)(bbv * EE + n + 1) << 12);
#pragma unroll
            for (int mt = 0; mt < 4; mt++) {
                const int t = tbase + mt * 16 + g;
                c0[t]     = acc[mt][nt][0] + b0;
                c1[t]     = acc[mt][nt][1] + b1;
                c0[t + 8] = acc[mt][nt][2] + b0;
                c1[t + 8] = acc[mt][nt][3] + b1;
            }
        }
    } else {
        // fp16 output C[m,n]
        __half* Ch = (__half*)C;
#pragma unroll
        for (int nt = 0; nt < 8; nt++) {
            const int n  = n0 + wn + nt * 8 + 2 * t4;
            const float b0 = __ldg(bias + n);
            const float b1 = __ldg(bias + n + 1);
#pragma unroll
            for (int mt = 0; mt < 4; mt++) {
                const int mrow = m0 + wm + mt * 16 + g;
                *(__half2*)&Ch[(size_t)mrow * EE + n] =
                    __floats2half2_rn(acc[mt][nt][0] + b0, acc[mt][nt][1] + b1);
                *(__half2*)&Ch[(size_t)(mrow + 8) * EE + n] =
                    __floats2half2_rn(acc[mt][nt][2] + b0, acc[mt][nt][3] + b1);
            }
        }
    }
}

// ===================== radix-4 4096-pt FFT (input digit-reversed base 4) ==========
// 6 stages, 1024 butterflies/stage, 512 threads (2 butterflies each).
__device__ __forceinline__ void fft4096_r4(float2* s, int tid) {
    int l2m = 0;
    for (int m = 1; m < 4096; m <<= 2, l2m += 2) {
#pragma unroll
        for (int u = 0; u < 2; u++) {
            int bi   = tid + (u << 9);
            int j    = bi & (m - 1);
            int base = ((bi >> l2m) << (l2m + 2)) | j;
            float2 x0 = s[base];
            float2 x1 = s[base + m];
            float2 x2 = s[base + 2 * m];
            float2 x3 = s[base + 3 * m];
            int e = j << (10 - l2m);          // j * (1024/m), < 1024
            float2 w1 = g_tw[e];
            float2 w2 = g_tw[2 * e];          // 2e < 2048: in table
            float2 w3 = cmulf(w1, w2);
            float2 t1 = cmulf(x1, w1);
            float2 t2 = cmulf(x2, w2);
            float2 t3 = cmulf(x3, w3);
            float2 a = make_float2(x0.x + t2.x, x0.y + t2.y);
            float2 b = make_float2(x0.x - t2.x, x0.y - t2.y);
            float2 c = make_float2(t1.x + t3.x, t1.y + t3.y);
            float2 d = make_float2(t1.x - t3.x, t1.y - t3.y);
            s[base]         = make_float2(a.x + c.x, a.y + c.y);
            s[base + 2 * m] = make_float2(a.x - c.x, a.y - c.y);
            s[base + m]     = make_float2(b.x + d.y, b.y - d.x);  // b - i*d
            s[base + 3 * m] = make_float2(b.x - d.y, b.y + d.x);  // b + i*d
        }
        __syncthreads();
    }
}

// base-4 digit reversal of a 12-bit index
__device__ __forceinline__ int digrev4(int i) {
    int r = __brev(i) >> 20;                           // 12-bit bit reversal
    return ((r & 0x555) << 1) | ((r & 0xAAA) >> 1);    // swap bit pairs
}

// ===================== forward correlation spectrum (q + i*k pack trick) ==========
__global__ void __launch_bounds__(512) corrfft_kernel() {
    __shared__ float2 s[4096];
    const int tid = threadIdx.x;
    const int b   = blockIdx.x >> 7;
    const int e0  = (blockIdx.x & 127) * 8;

    float2 psum[8];
#pragma unroll
    for (int r = 0; r < 8; r++) psum[r] = make_float2(0.f, 0.f);

    for (int c = 0; c < 8; c++) {
        const int ch = e0 + c;
        const float* q = g_Qt + ((size_t)(b * 1024 + ch)) * 4096;
        const float* k = g_Kt + ((size_t)(b * 1024 + ch)) * 4096;
        __syncthreads();   // previous product phase done before overwriting s
        for (int i = tid; i < 4096; i += 512)
            s[digrev4(i)] = make_float2(q[i], k[i]);
        __syncthreads();
        fft4096_r4(s, tid);
#pragma unroll
        for (int r = 0; r < 8; r++) {
            int f = tid + (r << 9);
            float2 A  = s[f];
            float2 Bc = s[(4096 - f) & 4095];
            float qr = 0.5f * (A.x + Bc.x);
            float qi = 0.5f * (A.y - Bc.y);
            float kr = 0.5f * (A.y + Bc.y);
            float ki = 0.5f * (Bc.x - A.x);
            psum[r].x += qr * kr + qi * ki;
            psum[r].y += qi * kr - qr * ki;
        }
    }

    float2* spec = g_spec + b * 4096;
#pragma unroll
    for (int r = 0; r < 8; r++) {
        int f = tid + (r << 9);
        atomicAdd(&spec[f].x, psum[r].x);
        atomicAdd(&spec[f].y, psum[r].y);
    }
}

__global__ void __launch_bounds__(512) ifft_kernel() {
    __shared__ float2 s[4096];
    const int b   = blockIdx.x;
    const int tid = threadIdx.x;
    for (int i = tid; i < 4096; i += 512) {
        float2 v = g_spec[b * 4096 + i];
        s[digrev4(i)] = make_float2(v.x, -v.y);   // conj -> fwd fft -> Re = Re(ifft)*N
    }
    __syncthreads();
    fft4096_r4(s, tid);
    const float scale = 1.0f / ((float)TT * (float)EE);
    for (int i = tid; i < 4096; i += 512)
        g_mean[b * 4096 + i] = s[i].x * scale;
}

// ===================== top-24 per batch =====================
__global__ void __launch_bounds__(256) topk_kernel() {
    __shared__ float sv[4096];
    __shared__ float rv[256];
    __shared__ int   ri[256];
    const int b   = blockIdx.x;
    const int tid = threadIdx.x;
    for (int i = tid; i < 4096; i += 256) sv[i] = g_mean[b * 4096 + i];
    __syncthreads();
    for (int kk = 0; kk < KTOP; kk++) {
        float best = -3.4e38f;
        int   bi   = 0;
        for (int i = tid; i < 4096; i += 256) {
            float v = sv[i];
            if (v > best) { best = v; bi = i; }
        }
        rv[tid] = best; ri[tid] = bi;
        __syncthreads();
        for (int st = 128; st > 0; st >>= 1) {
            if (tid < st) {
                float ov = rv[tid + st]; int oi = ri[tid + st];
                if (ov > rv[tid] || (ov == rv[tid] && oi < ri[tid])) {
                    rv[tid] = ov; ri[tid] = oi;
                }
            }
            __syncthreads();
        }
        if (tid == 0) {
            g_topv[b * KTOP + kk] = rv[0];
            g_topi[b * KTOP + kk] = ri[0];
            sv[ri[0]] = -3.4e38f;
        }
        __syncthreads();
    }
}

// agg[b,t,e] = sum_k w[g,k] * V[b,(t+d[g,k])%T,e],  g = (e/64)%8; V fp16 -> agg fp16
__global__ void __launch_bounds__(128) agg_kernel() {
    __shared__ float ws[8 * KTOP];
    __shared__ int   ds[8 * KTOP];
    const int tid = threadIdx.x;
    for (int i = tid; i < 8 * KTOP; i += 128) { ws[i] = g_topv[i]; ds[i] = g_topi[i]; }
    __syncthreads();

    const int bt = blockIdx.x;
    const int b  = bt >> 12;
    const int t  = bt & 4095;
    const int e8 = tid << 3;
    const int gg = (e8 >> 6) & 7;

    const __half* Vb = g_Vh + (size_t)b * TT * EE;
    float acc[8];
#pragma unroll
    for (int i = 0; i < 8; i++) acc[i] = 0.f;

#pragma unroll
    for (int kk = 0; kk < KTOP; kk++) {
        int   tk = (t + ds[gg * KTOP + kk]) & 4095;
        float w  = ws[gg * KTOP + kk];
        uint4 raw = *(const uint4*)&Vb[(size_t)tk * EE + e8];
        __half2 h0, h1, h2, h3;
        *(uint32_t*)&h0 = raw.x; *(uint32_t*)&h1 = raw.y;
        *(uint32_t*)&h2 = raw.z; *(uint32_t*)&h3 = raw.w;
        float2 f0 = __half22float2(h0), f1 = __half22float2(h1);
        float2 f2 = __half22float2(h2), f3 = __half22float2(h3);
        acc[0] += w * f0.x; acc[1] += w * f0.y;
        acc[2] += w * f1.x; acc[3] += w * f1.y;
        acc[4] += w * f2.x; acc[5] += w * f2.y;
        acc[6] += w * f3.x; acc[7] += w * f3.y;
    }

    __half2 p0 = __floats2half2_rn(acc[0], acc[1]);
    __half2 p1 = __floats2half2_rn(acc[2], acc[3]);
    __half2 p2 = __floats2half2_rn(acc[4], acc[5]);
    __half2 p3 = __floats2half2_rn(acc[6], acc[7]);
    uint4 outv = make_uint4(*(uint32_t*)&p0, *(uint32_t*)&p1,
                            *(uint32_t*)&p2, *(uint32_t*)&p3);
    *(uint4*)(g_aggh + (size_t)bt * EE + e8) = outv;
}

// ===================== launch =====================
extern "C" void kernel_launch(void* const* d_in, const int* in_sizes, int n_in,
                              void* d_out, int out_size) {
    (void)in_sizes; (void)n_in; (void)out_size;
    const float* hs = (const float*)d_in[0];
    const float* Wq = (const float*)d_in[1];
    const float* bq = (const float*)d_in[2];
    const float* Wk = (const float*)d_in[3];
    const float* bk = (const float*)d_in[4];
    const float* Wv = (const float*)d_in[5];
    const float* bv = (const float*)d_in[6];
    const float* Wo = (const float*)d_in[7];
    const float* bo = (const float*)d_in[8];
    float* out = (float*)d_out;

    cudaFuncSetAttribute(hgemm_kernel,
                         cudaFuncAttributeMaxDynamicSharedMemorySize, GEMM_SMEM);

    void *pXh, *pWth, *pQt, *pKt, *pVh, *pAggh;
    cudaGetSymbolAddress(&pXh,   g_Xh);
    cudaGetSymbolAddress(&pWth,  g_Wth);
    cudaGetSymbolAddress(&pQt,   g_Qt);
    cudaGetSymbolAddress(&pKt,   g_Kt);
    cudaGetSymbolAddress(&pVh,   g_Vh);
    cudaGetSymbolAddress(&pAggh, g_aggh);

    init_kernel<<<(BB * TT + 255) / 256, 256>>>();
    half_x_kernel<<<(BB * TT * EE / 4) / 256, 256>>>(hs);

    const dim3 tgrid(EE / 32, EE / 32);
    const dim3 tblk(32, 8);
    const dim3 ggrid(EE / BN, (BB * TT) / BM);

    transpose_half_kernel<<<tgrid, tblk>>>(Wq);
    hgemm_kernel<<<ggrid, 256, GEMM_SMEM>>>((const __half*)pXh, (const __half*)pWth, bq, (float*)pQt, 1);

    transpose_half_kernel<<<tgrid, tblk>>>(Wk);
    hgemm_kernel<<<ggrid, 256, GEMM_SMEM>>>((const __half*)pXh, (const __half*)pWth, bk, (float*)pKt, 1);

    transpose_half_kernel<<<tgrid, tblk>>>(Wv);
    hgemm_kernel<<<ggrid, 256, GEMM_SMEM>>>((const __half*)pXh, (const __half*)pWth, bv, (float*)pVh, 2);

    corrfft_kernel<<<BB * 128, 512>>>();
    ifft_kernel<<<BB, 512>>>();
    topk_kernel<<<BB, 256>>>();
    agg_kernel<<<BB * TT, 128>>>();

    transpose_half_kernel<<<tgrid, tblk>>>(Wo);
    hgemm_kernel<<<ggrid, 256, GEMM_SMEM>>>((const __half*)pAggh, (const __half*)pWth, bo, out, 0);
}

// round 10
// speedup vs baseline: 1.8418x; 1.0109x over previous
#include <cuda_runtime.h>
#include <cuda_fp16.h>
#include <math.h>
#include <stdint.h>

#ifndef M_PI
#define M_PI 3.14159265358979323846
#endif

#define BB   8
#define TT   4096
#define EE   1024
#define HH   16
#define DD   64
#define KTOP 24

// ===================== scratch (device globals) =====================
__device__ __align__(16) __half g_Xh  [BB * TT * EE];  // fp16 hidden_states
__device__ __align__(16) __half g_Wth [EE * EE];       // current transposed fp16 weight
__device__ __align__(16) __half g_Vh  [BB * TT * EE];  // fp16 V
__device__ __align__(16) __half g_aggh[BB * TT * EE];  // fp16 aggregated
__device__ float  g_Qt [BB * EE * TT];   // Q transposed: [b][e][t]  (fp32)
__device__ float  g_Kt [BB * EE * TT];   // K transposed: [b][e][t]  (fp32)
__device__ float2 g_spec[BB * TT];
__device__ float2 g_tw [TT / 2];
__device__ float  g_mean[BB * TT];
__device__ float  g_topv[BB * KTOP];
__device__ int    g_topi[BB * KTOP];

// ===================== helpers =====================
#define CP16(saddr, gptr) \
    asm volatile("cp.async.cg.shared.global [%0], [%1], 16;" :: "r"(saddr), "l"(gptr) : "memory")
#define CP_COMMIT() asm volatile("cp.async.commit_group;" ::: "memory")
#define CP_WAIT1()  asm volatile("cp.async.wait_group 1;" ::: "memory")

#define LDSM4(r0, r1, r2, r3, addr) \
    asm volatile("ldmatrix.sync.aligned.m8n8.x4.shared.b16 {%0,%1,%2,%3}, [%4];" \
        : "=r"(r0), "=r"(r1), "=r"(r2), "=r"(r3) : "r"(addr))

__device__ __forceinline__ uint32_t smem_u32(const void* p) {
    uint32_t a;
    asm("{ .reg .u64 t; cvta.to.shared.u64 t, %1; cvt.u32.u64 %0, t; }" : "=r"(a) : "l"(p));
    return a;
}

__device__ __forceinline__ void mma_f16(float* d, const uint32_t* a, const uint32_t* b) {
    asm volatile(
        "mma.sync.aligned.m16n8k16.row.col.f32.f16.f16.f32 "
        "{%0,%1,%2,%3}, {%4,%5,%6,%7}, {%8,%9}, {%0,%1,%2,%3};"
        : "+f"(d[0]), "+f"(d[1]), "+f"(d[2]), "+f"(d[3])
        : "r"(a[0]), "r"(a[1]), "r"(a[2]), "r"(a[3]), "r"(b[0]), "r"(b[1]));
}

__device__ __forceinline__ float2 cmulf(float2 a, float2 b) {
    return make_float2(a.x * b.x - a.y * b.y, a.x * b.y + a.y * b.x);
}

// ===================== init =====================
__global__ void init_kernel() {
    int i = blockIdx.x * blockDim.x + threadIdx.x;
    if (i < BB * TT) g_spec[i] = make_float2(0.f, 0.f);
    if (i < TT / 2) {
        double ang = -2.0 * M_PI * (double)i / (double)TT;
        double s, c;
        sincos(ang, &s, &c);
        g_tw[i] = make_float2((float)c, (float)s);
    }
}

// convert hidden_states to fp16
__global__ void __launch_bounds__(256) half_x_kernel(const float* __restrict__ src) {
    size_t i4 = ((size_t)blockIdx.x * blockDim.x + threadIdx.x) * 4;
    float4 v = *(const float4*)(src + i4);
    __half2* o = (__half2*)(g_Xh + i4);
    o[0] = __floats2half2_rn(v.x, v.y);
    o[1] = __floats2half2_rn(v.z, v.w);
}

// Wth[n][k] = half(W[k][n])
__global__ void __launch_bounds__(256) transpose_half_kernel(const float* __restrict__ W) {
    __shared__ float ts[32][33];
    int x  = blockIdx.x * 32 + threadIdx.x;   // n
    int y0 = blockIdx.y * 32;                 // k
    for (int i = threadIdx.y; i < 32; i += 8)
        ts[i][threadIdx.x] = W[(size_t)(y0 + i) * EE + x];
    __syncthreads();
    int xo = y0 + threadIdx.x;                // k out
    int yo = blockIdx.x * 32;                 // n out
    for (int i = threadIdx.y; i < 32; i += 8)
        g_Wth[(size_t)(yo + i) * EE + xo] = __float2half_rn(ts[threadIdx.x][i]);
}

// ===================== fp16 mma.sync GEMM (ldmatrix fragments) =====================
// C[M=32768, N=1024] = A[M,K=1024] * Bt[N,K]^T + bias   (A, Bt fp16)
// CTA 128x256, warp 64x64 (2x4 warps), K staged 64, 3-stage cp.async,
// single barrier per stage. outmode: 0 = fp32 C[m,n]; 1 = fp32 transposed
// per batch C[((b*E+n)*T)+t]; 2 = fp16 C[m,n].
#define BM 128
#define BN 256
#define BK 64
#define NSTG 3
#define A_WST 36                       // 32-bit words per A row (32 data + 4 pad)
#define B_WST 36
#define A_WORDS (BM * A_WST)           // 4608
#define B_WORDS (BN * B_WST)           // 9216
#define STG_WORDS (A_WORDS + B_WORDS)  // 13824
#define GEMM_SMEM (NSTG * STG_WORDS * 4)   // 165888 B

__global__ void __launch_bounds__(256, 1)
hgemm_kernel(const __half* __restrict__ A, const __half* __restrict__ Bt,
             const float* __restrict__ bias, float* __restrict__ C, int outmode)
{
    extern __shared__ uint32_t smw[];
    const int tid  = threadIdx.x;
    const int wid  = tid >> 5;
    const int lane = tid & 31;
    const int g    = lane >> 2;     // 0..7
    const int t4   = lane & 3;      // 0..3
    const int m0   = blockIdx.y * BM;
    const int n0   = blockIdx.x * BN;
    const int wm   = (wid >> 2) * 64;
    const int wn   = (wid & 3) * 64;

    const __half* gA = A  + (size_t)m0 * EE;
    const __half* gB = Bt + (size_t)n0 * EE;

    const uint32_t sbase = smem_u32(smw);

    // per-lane ldmatrix byte offsets (loop-invariant)
    // A x4 matrices: (m0-7,klo),(m8-15,klo),(m0-7,khi),(m8-15,khi)
    const uint32_t aLane = ((wm + (lane & 7) + ((lane >> 3) & 1) * 8) * A_WST
                           + ((lane >> 4) & 1) * 4) * 4;
    // B x4 matrices: (nt,klo),(nt,khi),(nt+1,klo),(nt+1,khi)
    const uint32_t bLane = ((wn + (lane & 7) + ((lane >> 4) & 1) * 8) * B_WST
                           + ((lane >> 3) & 1) * 4) * 4;

    // load K-slice [kt*64, kt*64+64) halves of every row into stage buffer
    auto load_stage = [&](int kt) {
        const int st = kt % NSTG;
        const uint32_t sA = sbase + st * STG_WORDS * 4;
        const uint32_t sB = sA + A_WORDS * 4;
        const __half* ga = gA + kt * BK;
        const __half* gb = gB + kt * BK;
#pragma unroll
        for (int i = 0; i < 4; i++) {           // A: 128 rows x 8 chunks
            int q = tid + (i << 8);
            int r = q >> 3, c = q & 7;
            CP16(sA + (r * A_WST + c * 4) * 4, ga + (size_t)r * EE + c * 8);
        }
#pragma unroll
        for (int i = 0; i < 8; i++) {           // B: 256 rows x 8 chunks
            int q = tid + (i << 8);
            int r = q >> 3, c = q & 7;
            CP16(sB + (r * B_WST + c * 4) * 4, gb + (size_t)r * EE + c * 8);
        }
    };

    float acc[4][8][4];
#pragma unroll
    for (int mt = 0; mt < 4; mt++)
#pragma unroll
        for (int nt = 0; nt < 8; nt++)
#pragma unroll
            for (int i = 0; i < 4; i++) acc[mt][nt][i] = 0.f;

    load_stage(0); CP_COMMIT();
    load_stage(1); CP_COMMIT();

    const int KT = EE / BK;   // 16
    for (int kt = 0; kt < KT; kt++) {
        CP_WAIT1();
        __syncthreads();      // stage kt visible; prior-stage readers done
        if (kt + 2 < KT) load_stage(kt + 2);
        CP_COMMIT();

        const uint32_t stA = sbase + (kt % NSTG) * STG_WORDS * 4;
        const uint32_t aBase = stA + aLane;
        const uint32_t bBase = stA + A_WORDS * 4 + bLane;

#pragma unroll
        for (int ks = 0; ks < 4; ks++) {        // four k16 chunks per stage
            const uint32_t ko = ks * 32;        // 8 words = 32 bytes
            uint32_t af[4][4], bf[8][2];
#pragma unroll
            for (int mt = 0; mt < 4; mt++)
                LDSM4(af[mt][0], af[mt][1], af[mt][2], af[mt][3],
                      aBase + mt * (16 * A_WST * 4) + ko);
#pragma unroll
            for (int ntp = 0; ntp < 4; ntp++)
                LDSM4(bf[2 * ntp][0], bf[2 * ntp][1],
                      bf[2 * ntp + 1][0], bf[2 * ntp + 1][1],
                      bBase + ntp * (16 * B_WST * 4) + ko);
#pragma unroll
            for (int mt = 0; mt < 4; mt++)
#pragma unroll
                for (int nt = 0; nt < 8; nt++)
                    mma_f16(acc[mt][nt], af[mt], bf[nt]);
        }
    }

    // ---- epilogue ----
    if (outmode == 0) {
#pragma unroll
        for (int nt = 0; nt < 8; nt++) {
            const int n  = n0 + wn + nt * 8 + 2 * t4;
            const float b0 = __ldg(bias + n);
            const float b1 = __ldg(bias + n + 1);
#pragma unroll
            for (int mt = 0; mt < 4; mt++) {
                const int mrow = m0 + wm + mt * 16 + g;
                float2 v0 = make_float2(acc[mt][nt][0] + b0, acc[mt][nt][1] + b1);
                float2 v1 = make_float2(acc[mt][nt][2] + b0, acc[mt][nt][3] + b1);
                *(float2*)&C[(size_t)mrow * EE + n]       = v0;
                *(float2*)&C[(size_t)(mrow + 8) * EE + n] = v1;
            }
        }
    } else if (outmode == 1) {
        // transposed per batch: C[((b*E + n) * T) + t]
        const int bbv   = m0 >> 12;
        const int tbase = (m0 & 4095) + wm;
#pragma unroll
        for (int nt = 0; nt < 8; nt++) {
            const int n  = n0 + wn + nt * 8 + 2 * t4;
            const float b0 = __ldg(bias + n);
            const float b1 = __ldg(bias + n + 1);
            float* c0 = C + ((size_t)(bbv * EE + n) << 12);
            float* c1 = C + ((size_t)(bbv * EE + n + 1) << 12);
#pragma unroll
            for (int mt = 0; mt < 4; mt++) {
                const int t = tbase + mt * 16 + g;
                c0[t]     = acc[mt][nt][0] + b0;
                c1[t]     = acc[mt][nt][1] + b1;
                c0[t + 8] = acc[mt][nt][2] + b0;
                c1[t + 8] = acc[mt][nt][3] + b1;
            }
        }
    } else {
        // fp16 output C[m,n]
        __half* Ch = (__half*)C;
#pragma unroll
        for (int nt = 0; nt < 8; nt++) {
            const int n  = n0 + wn + nt * 8 + 2 * t4;
            const float b0 = __ldg(bias + n);
            const float b1 = __ldg(bias + n + 1);
#pragma unroll
            for (int mt = 0; mt < 4; mt++) {
                const int mrow = m0 + wm + mt * 16 + g;
                *(__half2*)&Ch[(size_t)mrow * EE + n] =
                    __floats2half2_rn(acc[mt][nt][0] + b0, acc[mt][nt][1] + b1);
                *(__half2*)&Ch[(size_t)(mrow + 8) * EE + n] =
                    __floats2half2_rn(acc[mt][nt][2] + b0, acc[mt][nt][3] + b1);
            }
        }
    }
}

// ===================== radix-4 4096-pt FFT (input digit-reversed base 4) ==========
__device__ __forceinline__ void fft4096_r4(float2* s, int tid) {
    int l2m = 0;
    for (int m = 1; m < 4096; m <<= 2, l2m += 2) {
#pragma unroll
        for (int u = 0; u < 2; u++) {
            int bi   = tid + (u << 9);
            int j    = bi & (m - 1);
            int base = ((bi >> l2m) << (l2m + 2)) | j;
            float2 x0 = s[base];
            float2 x1 = s[base + m];
            float2 x2 = s[base + 2 * m];
            float2 x3 = s[base + 3 * m];
            int e = j << (10 - l2m);
            float2 w1 = g_tw[e];
            float2 w2 = g_tw[2 * e];
            float2 w3 = cmulf(w1, w2);
            float2 t1 = cmulf(x1, w1);
            float2 t2 = cmulf(x2, w2);
            float2 t3 = cmulf(x3, w3);
            float2 a = make_float2(x0.x + t2.x, x0.y + t2.y);
            float2 b = make_float2(x0.x - t2.x, x0.y - t2.y);
            float2 c = make_float2(t1.x + t3.x, t1.y + t3.y);
            float2 d = make_float2(t1.x - t3.x, t1.y - t3.y);
            s[base]         = make_float2(a.x + c.x, a.y + c.y);
            s[base + 2 * m] = make_float2(a.x - c.x, a.y - c.y);
            s[base + m]     = make_float2(b.x + d.y, b.y - d.x);
            s[base + 3 * m] = make_float2(b.x - d.y, b.y + d.x);
        }
        __syncthreads();
    }
}

__device__ __forceinline__ int digrev4(int i) {
    int r = __brev(i) >> 20;
    return ((r & 0x555) << 1) | ((r & 0xAAA) >> 1);
}

// ===================== forward correlation spectrum (q + i*k pack trick) ==========
__global__ void __launch_bounds__(512) corrfft_kernel() {
    __shared__ float2 s[4096];
    const int tid = threadIdx.x;
    const int b   = blockIdx.x >> 7;
    const int e0  = (blockIdx.x & 127) * 8;

    float2 psum[8];
#pragma unroll
    for (int r = 0; r < 8; r++) psum[r] = make_float2(0.f, 0.f);

    for (int c = 0; c < 8; c++) {
        const int ch = e0 + c;
        const float* q = g_Qt + ((size_t)(b * 1024 + ch)) * 4096;
        const float* k = g_Kt + ((size_t)(b * 1024 + ch)) * 4096;
        __syncthreads();
        for (int i = tid; i < 4096; i += 512)
            s[digrev4(i)] = make_float2(q[i], k[i]);
        __syncthreads();
        fft4096_r4(s, tid);
#pragma unroll
        for (int r = 0; r < 8; r++) {
            int f = tid + (r << 9);
            float2 A  = s[f];
            float2 Bc = s[(4096 - f) & 4095];
            float qr = 0.5f * (A.x + Bc.x);
            float qi = 0.5f * (A.y - Bc.y);
            float kr = 0.5f * (A.y + Bc.y);
            float ki = 0.5f * (Bc.x - A.x);
            psum[r].x += qr * kr + qi * ki;
            psum[r].y += qi * kr - qr * ki;
        }
    }

    float2* spec = g_spec + b * 4096;
#pragma unroll
    for (int r = 0; r < 8; r++) {
        int f = tid + (r << 9);
        atomicAdd(&spec[f].x, psum[r].x);
        atomicAdd(&spec[f].y, psum[r].y);
    }
}

__global__ void __launch_bounds__(512) ifft_kernel() {
    __shared__ float2 s[4096];
    const int b   = blockIdx.x;
    const int tid = threadIdx.x;
    for (int i = tid; i < 4096; i += 512) {
        float2 v = g_spec[b * 4096 + i];
        s[digrev4(i)] = make_float2(v.x, -v.y);
    }
    __syncthreads();
    fft4096_r4(s, tid);
    const float scale = 1.0f / ((float)TT * (float)EE);
    for (int i = tid; i < 4096; i += 512)
        g_mean[b * 4096 + i] = s[i].x * scale;
}

// ===================== top-24 per batch =====================
__global__ void __launch_bounds__(256) topk_kernel() {
    __shared__ float sv[4096];
    __shared__ float rv[256];
    __shared__ int   ri[256];
    const int b   = blockIdx.x;
    const int tid = threadIdx.x;
    for (int i = tid; i < 4096; i += 256) sv[i] = g_mean[b * 4096 + i];
    __syncthreads();
    for (int kk = 0; kk < KTOP; kk++) {
        float best = -3.4e38f;
        int   bi   = 0;
        for (int i = tid; i < 4096; i += 256) {
            float v = sv[i];
            if (v > best) { best = v; bi = i; }
        }
        rv[tid] = best; ri[tid] = bi;
        __syncthreads();
        for (int st = 128; st > 0; st >>= 1) {
            if (tid < st) {
                float ov = rv[tid + st]; int oi = ri[tid + st];
                if (ov > rv[tid] || (ov == rv[tid] && oi < ri[tid])) {
                    rv[tid] = ov; ri[tid] = oi;
                }
            }
            __syncthreads();
        }
        if (tid == 0) {
            g_topv[b * KTOP + kk] = rv[0];
            g_topi[b * KTOP + kk] = ri[0];
            sv[ri[0]] = -3.4e38f;
        }
        __syncthreads();
    }
}

// agg[b,t,e] = sum_k w[g,k] * V[b,(t+d[g,k])%T,e],  g = (e/64)%8; V fp16 -> agg fp16
__global__ void __launch_bounds__(128) agg_kernel() {
    __shared__ float ws[8 * KTOP];
    __shared__ int   ds[8 * KTOP];
    const int tid = threadIdx.x;
    for (int i = tid; i < 8 * KTOP; i += 128) { ws[i] = g_topv[i]; ds[i] = g_topi[i]; }
    __syncthreads();

    const int bt = blockIdx.x;
    const int b  = bt >> 12;
    const int t  = bt & 4095;
    const int e8 = tid << 3;
    const int gg = (e8 >> 6) & 7;

    const __half* Vb = g_Vh + (size_t)b * TT * EE;
    float acc[8];
#pragma unroll
    for (int i = 0; i < 8; i++) acc[i] = 0.f;

#pragma unroll
    for (int kk = 0; kk < KTOP; kk++) {
        int   tk = (t + ds[gg * KTOP + kk]) & 4095;
        float w  = ws[gg * KTOP + kk];
        uint4 raw = *(const uint4*)&Vb[(size_t)tk * EE + e8];
        __half2 h0, h1, h2, h3;
        *(uint32_t*)&h0 = raw.x; *(uint32_t*)&h1 = raw.y;
        *(uint32_t*)&h2 = raw.z; *(uint32_t*)&h3 = raw.w;
        float2 f0 = __half22float2(h0), f1 = __half22float2(h1);
        float2 f2 = __half22float2(h2), f3 = __half22float2(h3);
        acc[0] += w * f0.x; acc[1] += w * f0.y;
        acc[2] += w * f1.x; acc[3] += w * f1.y;
        acc[4] += w * f2.x; acc[5] += w * f2.y;
        acc[6] += w * f3.x; acc[7] += w * f3.y;
    }

    __half2 p0 = __floats2half2_rn(acc[0], acc[1]);
    __half2 p1 = __floats2half2_rn(acc[2], acc[3]);
    __half2 p2 = __floats2half2_rn(acc[4], acc[5]);
    __half2 p3 = __floats2half2_rn(acc[6], acc[7]);
    uint4 outv = make_uint4(*(uint32_t*)&p0, *(uint32_t*)&p1,
                            *(uint32_t*)&p2, *(uint32_t*)&p3);
    *(uint4*)(g_aggh + (size_t)bt * EE + e8) = outv;
}

// ===================== launch =====================
extern "C" void kernel_launch(void* const* d_in, const int* in_sizes, int n_in,
                              void* d_out, int out_size) {
    (void)in_sizes; (void)n_in; (void)out_size;
    const float* hs = (const float*)d_in[0];
    const float* Wq = (const float*)d_in[1];
    const float* bq = (const float*)d_in[2];
    const float* Wk = (const float*)d_in[3];
    const float* bk = (const float*)d_in[4];
    const float* Wv = (const float*)d_in[5];
    const float* bv = (const float*)d_in[6];
    const float* Wo = (const float*)d_in[7];
    const float* bo = (const float*)d_in[8];
    float* out = (float*)d_out;

    cudaFuncSetAttribute(hgemm_kernel,
                         cudaFuncAttributeMaxDynamicSharedMemorySize, GEMM_SMEM);

    void *pXh, *pWth, *pQt, *pKt, *pVh, *pAggh;
    cudaGetSymbolAddress(&pXh,   g_Xh);
    cudaGetSymbolAddress(&pWth,  g_Wth);
    cudaGetSymbolAddress(&pQt,   g_Qt);
    cudaGetSymbolAddress(&pKt,   g_Kt);
    cudaGetSymbolAddress(&pVh,   g_Vh);
    cudaGetSymbolAddress(&pAggh, g_aggh);

    init_kernel<<<(BB * TT + 255) / 256, 256>>>();
    half_x_kernel<<<(BB * TT * EE / 4) / 256, 256>>>(hs);

    const dim3 tgrid(EE / 32, EE / 32);
    const dim3 tblk(32, 8);
    const dim3 ggrid(EE / BN, (BB * TT) / BM);

    transpose_half_kernel<<<tgrid, tblk>>>(Wq);
    hgemm_kernel<<<ggrid, 256, GEMM_SMEM>>>((const __half*)pXh, (const __half*)pWth, bq, (float*)pQt, 1);

    transpose_half_kernel<<<tgrid, tblk>>>(Wk);
    hgemm_kernel<<<ggrid, 256, GEMM_SMEM>>>((const __half*)pXh, (const __half*)pWth, bk, (float*)pKt, 1);

    transpose_half_kernel<<<tgrid, tblk>>>(Wv);
    hgemm_kernel<<<ggrid, 256, GEMM_SMEM>>>((const __half*)pXh, (const __half*)pWth, bv, (float*)pVh, 2);

    corrfft_kernel<<<BB * 128, 512>>>();
    ifft_kernel<<<BB, 512>>>();
    topk_kernel<<<BB, 256>>>();
    agg_kernel<<<BB * TT, 128>>>();

    transpose_half_kernel<<<tgrid, tblk>>>(Wo);
    hgemm_kernel<<<ggrid, 256, GEMM_SMEM>>>((const __half*)pAggh, (const __half*)pWth, bo, out, 0);
}

// round 12
// speedup vs baseline: 1.9630x; 1.0658x over previous
#include <cuda_runtime.h>
#include <cuda_fp16.h>
#include <math.h>
#include <stdint.h>

#ifndef M_PI
#define M_PI 3.14159265358979323846
#endif

#define BB   8
#define TT   4096
#define EE   1024
#define HH   16
#define DD   64
#define KTOP 24

// ===================== scratch (device globals) =====================
__device__ __align__(16) __half g_Xh  [BB * TT * EE];   // fp16 hidden_states
__device__ __align__(16) __half g_Wth [4 * EE * EE];    // all 4 transposed fp16 weights
__device__ __align__(16) __half g_Qth [BB * EE * TT];   // Q transposed fp16: [b][e][t]
__device__ __align__(16) __half g_Kth [BB * EE * TT];   // K transposed fp16: [b][e][t]
__device__ __align__(16) __half g_Vh  [BB * TT * EE];   // fp16 V
__device__ __align__(16) __half g_aggh[BB * TT * EE];   // fp16 aggregated
__device__ float2 g_spec[BB * TT];
__device__ float2 g_tw [TT / 2];
__device__ float  g_topv[BB * KTOP];
__device__ int    g_topi[BB * KTOP];

// ===================== helpers =====================
#define CP16(saddr, gptr) \
    asm volatile("cp.async.cg.shared.global [%0], [%1], 16;" :: "r"(saddr), "l"(gptr) : "memory")
#define CP_COMMIT() asm volatile("cp.async.commit_group;" ::: "memory")
#define CP_WAIT1()  asm volatile("cp.async.wait_group 1;" ::: "memory")

#define LDSM4(r0, r1, r2, r3, addr) \
    asm volatile("ldmatrix.sync.aligned.m8n8.x4.shared.b16 {%0,%1,%2,%3}, [%4];" \
        : "=r"(r0), "=r"(r1), "=r"(r2), "=r"(r3) : "r"(addr))

__device__ __forceinline__ uint32_t smem_u32(const void* p) {
    uint32_t a;
    asm("{ .reg .u64 t; cvta.to.shared.u64 t, %1; cvt.u32.u64 %0, t; }" : "=r"(a) : "l"(p));
    return a;
}

__device__ __forceinline__ void mma_f16(float* d, const uint32_t* a, const uint32_t* b) {
    asm volatile(
        "mma.sync.aligned.m16n8k16.row.col.f32.f16.f16.f32 "
        "{%0,%1,%2,%3}, {%4,%5,%6,%7}, {%8,%9}, {%0,%1,%2,%3};"
        : "+f"(d[0]), "+f"(d[1]), "+f"(d[2]), "+f"(d[3])
        : "r"(a[0]), "r"(a[1]), "r"(a[2]), "r"(a[3]), "r"(b[0]), "r"(b[1]));
}

__device__ __forceinline__ float2 cmulf(float2 a, float2 b) {
    return make_float2(a.x * b.x - a.y * b.y, a.x * b.y + a.y * b.x);
}

// ===================== prep: fp16 X + zero spec + twiddles =====================
__global__ void __launch_bounds__(256) prep_kernel(const float* __restrict__ src) {
    int i = blockIdx.x * 256 + threadIdx.x;
    size_t i4 = (size_t)i * 4;
    float4 v = *(const float4*)(src + i4);
    __half2* o = (__half2*)(g_Xh + i4);
    o[0] = __floats2half2_rn(v.x, v.y);
    o[1] = __floats2half2_rn(v.z, v.w);
    if (i < BB * TT) g_spec[i] = make_float2(0.f, 0.f);
    if (i < TT / 2) {
        double ang = -2.0 * M_PI * (double)i / (double)TT;
        double s, c;
        sincos(ang, &s, &c);
        g_tw[i] = make_float2((float)c, (float)s);
    }
}

// all 4 weights: Wth[z][n][k] = half(W_z[k][n])
__global__ void __launch_bounds__(256) transpose4_kernel(
    const float* __restrict__ W0, const float* __restrict__ W1,
    const float* __restrict__ W2, const float* __restrict__ W3)
{
    __shared__ float ts[32][33];
    const float* W = (blockIdx.z == 0) ? W0 : (blockIdx.z == 1) ? W1
                   : (blockIdx.z == 2) ? W2 : W3;
    __half* dst = g_Wth + (size_t)blockIdx.z * EE * EE;
    int x  = blockIdx.x * 32 + threadIdx.x;   // n
    int y0 = blockIdx.y * 32;                 // k
    for (int i = threadIdx.y; i < 32; i += 8)
        ts[i][threadIdx.x] = W[(size_t)(y0 + i) * EE + x];
    __syncthreads();
    int xo = y0 + threadIdx.x;                // k out
    int yo = blockIdx.x * 32;                 // n out
    for (int i = threadIdx.y; i < 32; i += 8)
        dst[(size_t)(yo + i) * EE + xo] = __float2half_rn(ts[threadIdx.x][i]);
}

// ===================== fp16 mma.sync GEMM (ldmatrix fragments) =====================
// C[M=32768, N=1024] = A[M,K=1024] * Bt[N,K]^T + bias   (A, Bt fp16)
// outmode: 0 = fp32 C[m,n]; 1 = fp16 transposed per batch C[((b*E+n)*T)+t];
//          2 = fp16 C[m,n].
#define BM 128
#define BN 256
#define BK 64
#define NSTG 3
#define A_WST 36
#define B_WST 36
#define A_WORDS (BM * A_WST)
#define B_WORDS (BN * B_WST)
#define STG_WORDS (A_WORDS + B_WORDS)
#define GEMM_SMEM (NSTG * STG_WORDS * 4)   // 165888 B

__global__ void __launch_bounds__(256, 1)
hgemm_kernel(const __half* __restrict__ A, const __half* __restrict__ Bt,
             const float* __restrict__ bias, float* __restrict__ C, int outmode)
{
    extern __shared__ uint32_t smw[];
    const int tid  = threadIdx.x;
    const int wid  = tid >> 5;
    const int lane = tid & 31;
    const int g    = lane >> 2;
    const int t4   = lane & 3;
    const int m0   = blockIdx.y * BM;
    const int n0   = blockIdx.x * BN;
    const int wm   = (wid >> 2) * 64;
    const int wn   = (wid & 3) * 64;

    const __half* gA = A  + (size_t)m0 * EE;
    const __half* gB = Bt + (size_t)n0 * EE;

    const uint32_t sbase = smem_u32(smw);

    const uint32_t aLane = ((wm + (lane & 7) + ((lane >> 3) & 1) * 8) * A_WST
                           + ((lane >> 4) & 1) * 4) * 4;
    const uint32_t bLane = ((wn + (lane & 7) + ((lane >> 4) & 1) * 8) * B_WST
                           + ((lane >> 3) & 1) * 4) * 4;

    auto load_stage = [&](int kt) {
        const int st = kt % NSTG;
        const uint32_t sA = sbase + st * STG_WORDS * 4;
        const uint32_t sB = sA + A_WORDS * 4;
        const __half* ga = gA + kt * BK;
        const __half* gb = gB + kt * BK;
#pragma unroll
        for (int i = 0; i < 4; i++) {
            int q = tid + (i << 8);
            int r = q >> 3, c = q & 7;
            CP16(sA + (r * A_WST + c * 4) * 4, ga + (size_t)r * EE + c * 8);
        }
#pragma unroll
        for (int i = 0; i < 8; i++) {
            int q = tid + (i << 8);
            int r = q >> 3, c = q & 7;
            CP16(sB + (r * B_WST + c * 4) * 4, gb + (size_t)r * EE + c * 8);
        }
    };

    float acc[4][8][4];
#pragma unroll
    for (int mt = 0; mt < 4; mt++)
#pragma unroll
        for (int nt = 0; nt < 8; nt++)
#pragma unroll
            for (int i = 0; i < 4; i++) acc[mt][nt][i] = 0.f;

    load_stage(0); CP_COMMIT();
    load_stage(1); CP_COMMIT();

    const int KT = EE / BK;   // 16
    for (int kt = 0; kt < KT; kt++) {
        CP_WAIT1();
        __syncthreads();
        if (kt + 2 < KT) load_stage(kt + 2);
        CP_COMMIT();

        const uint32_t stA = sbase + (kt % NSTG) * STG_WORDS * 4;
        const uint32_t aBase = stA + aLane;
        const uint32_t bBase = stA + A_WORDS * 4 + bLane;

#pragma unroll
        for (int ks = 0; ks < 4; ks++) {
            const uint32_t ko = ks * 32;
            uint32_t af[4][4], bf[8][2];
#pragma unroll
            for (int mt = 0; mt < 4; mt++)
                LDSM4(af[mt][0], af[mt][1], af[mt][2], af[mt][3],
                      aBase + mt * (16 * A_WST * 4) + ko);
#pragma unroll
            for (int ntp = 0; ntp < 4; ntp++)
                LDSM4(bf[2 * ntp][0], bf[2 * ntp][1],
                      bf[2 * ntp + 1][0], bf[2 * ntp + 1][1],
                      bBase + ntp * (16 * B_WST * 4) + ko);
#pragma unroll
            for (int mt = 0; mt < 4; mt++)
#pragma unroll
                for (int nt = 0; nt < 8; nt++)
                    mma_f16(acc[mt][nt], af[mt], bf[nt]);
        }
    }

    // ---- epilogue ----
    if (outmode == 0) {
#pragma unroll
        for (int nt = 0; nt < 8; nt++) {
            const int n  = n0 + wn + nt * 8 + 2 * t4;
            const float b0 = __ldg(bias + n);
            const float b1 = __ldg(bias + n + 1);
#pragma unroll
            for (int mt = 0; mt < 4; mt++) {
                const int mrow = m0 + wm + mt * 16 + g;
                float2 v0 = make_float2(acc[mt][nt][0] + b0, acc[mt][nt][1] + b1);
                float2 v1 = make_float2(acc[mt][nt][2] + b0, acc[mt][nt][3] + b1);
                *(float2*)&C[(size_t)mrow * EE + n]       = v0;
                *(float2*)&C[(size_t)(mrow + 8) * EE + n] = v1;
            }
        }
    } else if (outmode == 1) {
        // fp16 transposed per batch: Ch[((b*E + n) * T) + t]
        __half* Ch = (__half*)C;
        const int bbv   = m0 >> 12;
        const int tbase = (m0 & 4095) + wm;
#pragma unroll
        for (int nt = 0; nt < 8; nt++) {
            const int n  = n0 + wn + nt * 8 + 2 * t4;
            const float b0 = __ldg(bias + n);
            const float b1 = __ldg(bias + n + 1);
            __half* c0 = Ch + ((size_t)(bbv * EE + n) << 12);
            __half* c1 = Ch + ((size_t)(bbv * EE + n + 1) << 12);
#pragma unroll
            for (int mt = 0; mt < 4; mt++) {
                const int t = tbase + mt * 16 + g;
                c0[t]     = __float2half_rn(acc[mt][nt][0] + b0);
                c1[t]     = __float2half_rn(acc[mt][nt][1] + b1);
                c0[t + 8] = __float2half_rn(acc[mt][nt][2] + b0);
                c1[t + 8] = __float2half_rn(acc[mt][nt][3] + b1);
            }
        }
    } else {
        // fp16 output C[m,n]
        __half* Ch = (__half*)C;
#pragma unroll
        for (int nt = 0; nt < 8; nt++) {
            const int n  = n0 + wn + nt * 8 + 2 * t4;
            const float b0 = __ldg(bias + n);
            const float b1 = __ldg(bias + n + 1);
#pragma unroll
            for (int mt = 0; mt < 4; mt++) {
                const int mrow = m0 + wm + mt * 16 + g;
                *(__half2*)&Ch[(size_t)mrow * EE + n] =
                    __floats2half2_rn(acc[mt][nt][0] + b0, acc[mt][nt][1] + b1);
                *(__half2*)&Ch[(size_t)(mrow + 8) * EE + n] =
                    __floats2half2_rn(acc[mt][nt][2] + b0, acc[mt][nt][3] + b1);
            }
        }
    }
}

// ===================== radix-4 4096-pt FFT, stages fully unrolled =====================
__device__ __forceinline__ void fft4096_r4(float2* s, int tid) {
#pragma unroll
    for (int st = 0; st < 6; st++) {
        const int l2m = 2 * st;
        const int m   = 1 << l2m;
#pragma unroll
        for (int u = 0; u < 2; u++) {
            int bi   = tid + (u << 9);
            int j    = bi & (m - 1);
            int base = ((bi >> l2m) << (l2m + 2)) | j;
            float2 x0 = s[base];
            float2 x1 = s[base + m];
            float2 x2 = s[base + 2 * m];
            float2 x3 = s[base + 3 * m];
            int e = j << (10 - l2m);
            float2 w1 = g_tw[e];
            float2 w2 = g_tw[2 * e];
            float2 w3 = cmulf(w1, w2);
            float2 t1 = cmulf(x1, w1);
            float2 t2 = cmulf(x2, w2);
            float2 t3 = cmulf(x3, w3);
            float2 a = make_float2(x0.x + t2.x, x0.y + t2.y);
            float2 b = make_float2(x0.x - t2.x, x0.y - t2.y);
            float2 c = make_float2(t1.x + t3.x, t1.y + t3.y);
            float2 d = make_float2(t1.x - t3.x, t1.y - t3.y);
            s[base]         = make_float2(a.x + c.x, a.y + c.y);
            s[base + 2 * m] = make_float2(a.x - c.x, a.y - c.y);
            s[base + m]     = make_float2(b.x + d.y, b.y - d.x);
            s[base + 3 * m] = make_float2(b.x - d.y, b.y + d.x);
        }
        __syncthreads();
    }
}

__device__ __forceinline__ int digrev4(int i) {
    int r = __brev(i) >> 20;
    return ((r & 0x555) << 1) | ((r & 0xAAA) >> 1);
}

// ===================== forward correlation spectrum (q + i*k pack trick) ==========
__global__ void __launch_bounds__(512) corrfft_kernel() {
    __shared__ float2 s[4096];
    const int tid = threadIdx.x;
    const int b   = blockIdx.x >> 7;
    const int e0  = (blockIdx.x & 127) * 8;

    float2 psum[8];
#pragma unroll
    for (int r = 0; r < 8; r++) psum[r] = make_float2(0.f, 0.f);

    for (int c = 0; c < 8; c++) {
        const int ch = e0 + c;
        const __half* q = g_Qth + ((size_t)(b * 1024 + ch)) * 4096;
        const __half* k = g_Kth + ((size_t)(b * 1024 + ch)) * 4096;
        __syncthreads();
        for (int i = tid; i < 4096; i += 512)
            s[digrev4(i)] = make_float2(__half2float(q[i]), __half2float(k[i]));
        __syncthreads();
        fft4096_r4(s, tid);
#pragma unroll
        for (int r = 0; r < 8; r++) {
            int f = tid + (r << 9);
            float2 A  = s[f];
            float2 Bc = s[(4096 - f) & 4095];
            float qr = 0.5f * (A.x + Bc.x);
            float qi = 0.5f * (A.y - Bc.y);
            float kr = 0.5f * (A.y + Bc.y);
            float ki = 0.5f * (Bc.x - A.x);
            psum[r].x += qr * kr + qi * ki;
            psum[r].y += qi * kr - qr * ki;
        }
    }

    float2* spec = g_spec + b * 4096;
#pragma unroll
    for (int r = 0; r < 8; r++) {
        int f = tid + (r << 9);
        atomicAdd(&spec[f].x, psum[r].x);
        atomicAdd(&spec[f].y, psum[r].y);
    }
}

// ===================== fused inverse FFT + top-24 =====================
__global__ void __launch_bounds__(512) ifft_topk_kernel() {
    __shared__ float2 s[4096];
    __shared__ float rv[16];
    __shared__ int   ri[16];
    __shared__ float bwv;
    __shared__ int   bwi;
    const int b    = blockIdx.x;
    const int tid  = threadIdx.x;
    const int wrp  = tid >> 5;
    const int lane = tid & 31;

    for (int i = tid; i < 4096; i += 512) {
        float2 v = g_spec[b * 4096 + i];
        s[digrev4(i)] = make_float2(v.x, -v.y);   // conj -> fwd fft -> Re = Re(ifft)*N
    }
    __syncthreads();
    fft4096_r4(s, tid);

    const float scale = 1.0f / ((float)TT * (float)EE);
    float val[8];
    int   idx[8];
#pragma unroll
    for (int r = 0; r < 8; r++) {
        int f  = tid + (r << 9);
        val[r] = s[f].x * scale;
        idx[r] = f;
    }

    for (int kk = 0; kk < KTOP; kk++) {
        float best = -3.4e38f;
        int   bi   = 0x7fffffff;
#pragma unroll
        for (int r = 0; r < 8; r++) {
            float v = val[r];
            if (v > best || (v == best && idx[r] < bi)) { best = v; bi = idx[r]; }
        }
#pragma unroll
        for (int off = 16; off > 0; off >>= 1) {
            float ov = __shfl_down_sync(0xFFFFFFFF, best, off);
            int   oi = __shfl_down_sync(0xFFFFFFFF, bi, off);
            if (ov > best || (ov == best && oi < bi)) { best = ov; bi = oi; }
        }
        if (lane == 0) { rv[wrp] = best; ri[wrp] = bi; }
        __syncthreads();
        if (wrp == 0) {
            float wv = (lane < 16) ? rv[lane] : -3.4e38f;
            int   wi = (lane < 16) ? ri[lane] : 0x7fffffff;
#pragma unroll
            for (int off = 8; off > 0; off >>= 1) {
                float ov = __shfl_down_sync(0xFFFFFFFF, wv, off);
                int   oi = __shfl_down_sync(0xFFFFFFFF, wi, off);
                if (ov > wv || (ov == wv && oi < wi)) { wv = ov; wi = oi; }
            }
            if (lane == 0) {
                g_topv[b * KTOP + kk] = wv;
                g_topi[b * KTOP + kk] = wi;
                bwv = wv; bwi = wi;
            }
        }
        __syncthreads();
        const int kill = bwi;
#pragma unroll
        for (int r = 0; r < 8; r++)
            if (idx[r] == kill) val[r] = -3.4e38f;
    }
}

// agg[b,t,e] = sum_k w[g,k] * V[b,(t+d[g,k])%T,e],  g = (e/64)%8; V fp16 -> agg fp16
__global__ void __launch_bounds__(128) agg_kernel() {
    __shared__ float ws[8 * KTOP];
    __shared__ int   ds[8 * KTOP];
    const int tid = threadIdx.x;
    for (int i = tid; i < 8 * KTOP; i += 128) { ws[i] = g_topv[i]; ds[i] = g_topi[i]; }
    __syncthreads();

    const int bt = blockIdx.x;
    const int b  = bt >> 12;
    const int t  = bt & 4095;
    const int e8 = tid << 3;
    const int gg = (e8 >> 6) & 7;

    const __half* Vb = g_Vh + (size_t)b * TT * EE;
    float acc[8];
#pragma unroll
    for (int i = 0; i < 8; i++) acc[i] = 0.f;

#pragma unroll
    for (int kk = 0; kk < KTOP; kk++) {
        int   tk = (t + ds[gg * KTOP + kk]) & 4095;
        float w  = ws[gg * KTOP + kk];
        uint4 raw = *(const uint4*)&Vb[(size_t)tk * EE + e8];
        __half2 h0, h1, h2, h3;
        *(uint32_t*)&h0 = raw.x; *(uint32_t*)&h1 = raw.y;
        *(uint32_t*)&h2 = raw.z; *(uint32_t*)&h3 = raw.w;
        float2 f0 = __half22float2(h0), f1 = __half22float2(h1);
        float2 f2 = __half22float2(h2), f3 = __half22float2(h3);
        acc[0] += w * f0.x; acc[1] += w * f0.y;
        acc[2] += w * f1.x; acc[3] += w * f1.y;
        acc[4] += w * f2.x; acc[5] += w * f2.y;
        acc[6] += w * f3.x; acc[7] += w * f3.y;
    }

    __half2 p0 = __floats2half2_rn(acc[0], acc[1]);
    __half2 p1 = __floats2half2_rn(acc[2], acc[3]);
    __half2 p2 = __floats2half2_rn(acc[4], acc[5]);
    __half2 p3 = __floats2half2_rn(acc[6], acc[7]);
    uint4 outv = make_uint4(*(uint32_t*)&p0, *(uint32_t*)&p1,
                            *(uint32_t*)&p2, *(uint32_t*)&p3);
    *(uint4*)(g_aggh + (size_t)bt * EE + e8) = outv;
}

// ===================== launch =====================
extern "C" void kernel_launch(void* const* d_in, const int* in_sizes, int n_in,
                              void* d_out, int out_size) {
    (void)in_sizes; (void)n_in; (void)out_size;
    const float* hs = (const float*)d_in[0];
    const float* Wq = (const float*)d_in[1];
    const float* bq = (const float*)d_in[2];
    const float* Wk = (const float*)d_in[3];
    const float* bk = (const float*)d_in[4];
    const float* Wv = (const float*)d_in[5];
    const float* bv = (const float*)d_in[6];
    const float* Wo = (const float*)d_in[7];
    const float* bo = (const float*)d_in[8];
    float* out = (float*)d_out;

    cudaFuncSetAttribute(hgemm_kernel,
                         cudaFuncAttributeMaxDynamicSharedMemorySize, GEMM_SMEM);

    void *pXh, *pWth, *pQth, *pKth, *pVh, *pAggh;
    cudaGetSymbolAddress(&pXh,   g_Xh);
    cudaGetSymbolAddress(&pWth,  g_Wth);
    cudaGetSymbolAddress(&pQth,  g_Qth);
    cudaGetSymbolAddress(&pKth,  g_Kth);
    cudaGetSymbolAddress(&pVh,   g_Vh);
    cudaGetSymbolAddress(&pAggh, g_aggh);

    const __half* Wth = (const __half*)pWth;

    prep_kernel<<<(BB * TT * EE / 4) / 256, 256>>>(hs);
    transpose4_kernel<<<dim3(EE / 32, EE / 32, 4), dim3(32, 8)>>>(Wq, Wk, Wv, Wo);

    const dim3 ggrid(EE / BN, (BB * TT) / BM);

    hgemm_kernel<<<ggrid, 256, GEMM_SMEM>>>((const __half*)pXh, Wth + 0 * EE * EE, bq, (float*)pQth, 1);
    hgemm_kernel<<<ggrid, 256, GEMM_SMEM>>>((const __half*)pXh, Wth + 1 * EE * EE, bk, (float*)pKth, 1);
    hgemm_kernel<<<ggrid, 256, GEMM_SMEM>>>((const __half*)pXh, Wth + 2 * EE * EE, bv, (float*)pVh,  2);

    corrfft_kernel<<<BB * 128, 512>>>();
    ifft_topk_kernel<<<BB, 512>>>();
    agg_kernel<<<BB * TT, 128>>>();

    hgemm_kernel<<<ggrid, 256, GEMM_SMEM>>>((const __half*)pAggh, Wth + 3 * EE * EE, bo, out, 0);
}

// round 15
// speedup vs baseline: 2.0726x; 1.0558x over previous
#include <cuda_runtime.h>
#include <cuda_fp16.h>
#include <math.h>
#include <stdint.h>

#ifndef M_PI
#define M_PI 3.14159265358979323846
#endif

#define BB   8
#define TT   4096
#define EE   1024
#define HH   16
#define DD   64
#define KTOP 24

// ===================== scratch (device globals) =====================
__device__ __align__(16) __half g_Xh  [BB * TT * EE];   // fp16 hidden_states
__device__ __align__(16) __half g_Wth [4 * EE * EE];    // all 4 transposed fp16 weights
__device__ __align__(16) __half g_Qth [BB * EE * TT];   // Q transposed fp16: [b][e][t]
__device__ __align__(16) __half g_Kth [BB * EE * TT];   // K transposed fp16: [b][e][t]
__device__ __align__(16) __half g_Vh  [BB * TT * EE];   // fp16 V
__device__ __align__(16) __half g_aggh[BB * TT * EE];   // fp16 aggregated
__device__ float2 g_spec[BB * TT];
__device__ float2 g_tw [TT / 2];
__device__ float  g_topv[BB * KTOP];
__device__ int    g_topi[BB * KTOP];

// ===================== helpers =====================
#define CP16(saddr, gptr) \
    asm volatile("cp.async.cg.shared.global [%0], [%1], 16;" :: "r"(saddr), "l"(gptr) : "memory")
#define CP_COMMIT() asm volatile("cp.async.commit_group;" ::: "memory")
#define CP_WAIT1()  asm volatile("cp.async.wait_group 1;" ::: "memory")

#define LDSM4(r0, r1, r2, r3, addr) \
    asm volatile("ldmatrix.sync.aligned.m8n8.x4.shared.b16 {%0,%1,%2,%3}, [%4];" \
        : "=r"(r0), "=r"(r1), "=r"(r2), "=r"(r3) : "r"(addr))

__device__ __forceinline__ uint32_t smem_u32(const void* p) {
    uint32_t a;
    asm("{ .reg .u64 t; cvta.to.shared.u64 t, %1; cvt.u32.u64 %0, t; }" : "=r"(a) : "l"(p));
    return a;
}

__device__ __forceinline__ void mma_f16(float* d, const uint32_t* a, const uint32_t* b) {
    asm volatile(
        "mma.sync.aligned.m16n8k16.row.col.f32.f16.f16.f32 "
        "{%0,%1,%2,%3}, {%4,%5,%6,%7}, {%8,%9}, {%0,%1,%2,%3};"
        : "+f"(d[0]), "+f"(d[1]), "+f"(d[2]), "+f"(d[3])
        : "r"(a[0]), "r"(a[1]), "r"(a[2]), "r"(a[3]), "r"(b[0]), "r"(b[1]));
}

__device__ __forceinline__ float2 cmulf(float2 a, float2 b) {
    return make_float2(a.x * b.x - a.y * b.y, a.x * b.y + a.y * b.x);
}

// ===================== prep: fp16 X + zero spec + twiddles =====================
__global__ void __launch_bounds__(256) prep_kernel(const float* __restrict__ src) {
    int i = blockIdx.x * 256 + threadIdx.x;
    size_t i4 = (size_t)i * 4;
    float4 v = *(const float4*)(src + i4);
    __half2* o = (__half2*)(g_Xh + i4);
    o[0] = __floats2half2_rn(v.x, v.y);
    o[1] = __floats2half2_rn(v.z, v.w);
    if (i < BB * TT) g_spec[i] = make_float2(0.f, 0.f);
    if (i < TT / 2) {
        double ang = -2.0 * M_PI * (double)i / (double)TT;
        double s, c;
        sincos(ang, &s, &c);
        g_tw[i] = make_float2((float)c, (float)s);
    }
}

// all 4 weights: Wth[z][n][k] = half(W_z[k][n])
__global__ void __launch_bounds__(256) transpose4_kernel(
    const float* __restrict__ W0, const float* __restrict__ W1,
    const float* __restrict__ W2, const float* __restrict__ W3)
{
    __shared__ float ts[32][33];
    const float* W = (blockIdx.z == 0) ? W0 : (blockIdx.z == 1) ? W1
                   : (blockIdx.z == 2) ? W2 : W3;
    __half* dst = g_Wth + (size_t)blockIdx.z * EE * EE;
    int x  = blockIdx.x * 32 + threadIdx.x;   // n
    int y0 = blockIdx.y * 32;                 // k
    for (int i = threadIdx.y; i < 32; i += 8)
        ts[i][threadIdx.x] = W[(size_t)(y0 + i) * EE + x];
    __syncthreads();
    int xo = y0 + threadIdx.x;                // k out
    int yo = blockIdx.x * 32;                 // n out
    for (int i = threadIdx.y; i < 32; i += 8)
        dst[(size_t)(yo + i) * EE + xo] = __float2half_rn(ts[threadIdx.x][i]);
}

// ===================== fp16 mma.sync GEMM (ldmatrix, 2 CTAs/SM) =====================
// C[M=32768, N=1024] = A[M,K=1024] * Bt[N,K]^T + bias   (A, Bt fp16)
// CTA 128x128, warp 64x32 (2x4 warps), K staged 64, 3-stage cp.async.
// outmode: 0 = fp32 C[m,n]; 1 = fp16 transposed per batch C[((b*E+n)*T)+t];
//          2 = fp16 C[m,n].
#define BM 128
#define BN 128
#define BK 64
#define NSTG 3
#define A_WST 36
#define B_WST 36
#define A_WORDS (BM * A_WST)              // 4608
#define B_WORDS (BN * B_WST)              // 4608
#define STG_WORDS (A_WORDS + B_WORDS)     // 9216
#define GEMM_SMEM (NSTG * STG_WORDS * 4)  // 110592 B -> 2 CTAs/SM

__global__ void __launch_bounds__(256, 2)
hgemm_kernel(const __half* __restrict__ A, const __half* __restrict__ Bt,
             const float* __restrict__ bias, float* __restrict__ C, int outmode)
{
    extern __shared__ uint32_t smw[];
    const int tid  = threadIdx.x;
    const int wid  = tid >> 5;
    const int lane = tid & 31;
    const int g    = lane >> 2;
    const int t4   = lane & 3;
    const int m0   = blockIdx.y * BM;
    const int n0   = blockIdx.x * BN;
    const int wm   = (wid >> 2) * 64;   // 0 or 64
    const int wn   = (wid & 3) * 32;    // 0,32,64,96

    const __half* gA = A  + (size_t)m0 * EE;
    const __half* gB = Bt + (size_t)n0 * EE;

    const uint32_t sbase = smem_u32(smw);

    const uint32_t aLane = ((wm + (lane & 7) + ((lane >> 3) & 1) * 8) * A_WST
                           + ((lane >> 4) & 1) * 4) * 4;
    const uint32_t bLane = ((wn + (lane & 7) + ((lane >> 4) & 1) * 8) * B_WST
                           + ((lane >> 3) & 1) * 4) * 4;

    auto load_stage = [&](int kt) {
        const int st = kt % NSTG;
        const uint32_t sA = sbase + st * STG_WORDS * 4;
        const uint32_t sB = sA + A_WORDS * 4;
        const __half* ga = gA + kt * BK;
        const __half* gb = gB + kt * BK;
#pragma unroll
        for (int i = 0; i < 4; i++) {          // A: 128 rows x 8 chunks
            int q = tid + (i << 8);
            int r = q >> 3, c = q & 7;
            CP16(sA + (r * A_WST + c * 4) * 4, ga + (size_t)r * EE + c * 8);
        }
#pragma unroll
        for (int i = 0; i < 4; i++) {          // B: 128 rows x 8 chunks
            int q = tid + (i << 8);
            int r = q >> 3, c = q & 7;
            CP16(sB + (r * B_WST + c * 4) * 4, gb + (size_t)r * EE + c * 8);
        }
    };

    float acc[4][4][4];
#pragma unroll
    for (int mt = 0; mt < 4; mt++)
#pragma unroll
        for (int nt = 0; nt < 4; nt++)
#pragma unroll
            for (int i = 0; i < 4; i++) acc[mt][nt][i] = 0.f;

    load_stage(0); CP_COMMIT();
    load_stage(1); CP_COMMIT();

    const int KT = EE / BK;   // 16
    for (int kt = 0; kt < KT; kt++) {
        CP_WAIT1();
        __syncthreads();
        if (kt + 2 < KT) load_stage(kt + 2);
        CP_COMMIT();

        const uint32_t stA = sbase + (kt % NSTG) * STG_WORDS * 4;
        const uint32_t aBase = stA + aLane;
        const uint32_t bBase = stA + A_WORDS * 4 + bLane;

#pragma unroll
        for (int ks = 0; ks < 4; ks++) {
            const uint32_t ko = ks * 32;
            uint32_t af[4][4], bf[4][2];
#pragma unroll
            for (int mt = 0; mt < 4; mt++)
                LDSM4(af[mt][0], af[mt][1], af[mt][2], af[mt][3],
                      aBase + mt * (16 * A_WST * 4) + ko);
#pragma unroll
            for (int ntp = 0; ntp < 2; ntp++)
                LDSM4(bf[2 * ntp][0], bf[2 * ntp][1],
                      bf[2 * ntp + 1][0], bf[2 * ntp + 1][1],
                      bBase + ntp * (16 * B_WST * 4) + ko);
#pragma unroll
            for (int mt = 0; mt < 4; mt++)
#pragma unroll
                for (int nt = 0; nt < 4; nt++)
                    mma_f16(acc[mt][nt], af[mt], bf[nt]);
        }
    }

    // ---- epilogue ----
    if (outmode == 0) {
#pragma unroll
        for (int nt = 0; nt < 4; nt++) {
            const int n  = n0 + wn + nt * 8 + 2 * t4;
            const float b0 = __ldg(bias + n);
            const float b1 = __ldg(bias + n + 1);
#pragma unroll
            for (int mt = 0; mt < 4; mt++) {
                const int mrow = m0 + wm + mt * 16 + g;
                float2 v0 = make_float2(acc[mt][nt][0] + b0, acc[mt][nt][1] + b1);
                float2 v1 = make_float2(acc[mt][nt][2] + b0, acc[mt][nt][3] + b1);
                *(float2*)&C[(size_t)mrow * EE + n]       = v0;
                *(float2*)&C[(size_t)(mrow + 8) * EE + n] = v1;
            }
        }
    } else if (outmode == 1) {
        // fp16 transposed per batch: Ch[((b*E + n) * T) + t]
        __half* Ch = (__half*)C;
        const int bbv   = m0 >> 12;
        const int tbase = (m0 & 4095) + wm;
#pragma unroll
        for (int nt = 0; nt < 4; nt++) {
            const int n  = n0 + wn + nt * 8 + 2 * t4;
            const float b0 = __ldg(bias + n);
            const float b1 = __ldg(bias + n + 1);
            __half* c0 = Ch + ((size_t)(bbv * EE + n) << 12);
            __half* c1 = Ch + ((size_t)(bbv * EE + n + 1) << 12);
#pragma unroll
            for (int mt = 0; mt < 4; mt++) {
                const int t = tbase + mt * 16 + g;
                c0[t]     = __float2half_rn(acc[mt][nt][0] + b0);
                c1[t]     = __float2half_rn(acc[mt][nt][1] + b1);
                c0[t + 8] = __float2half_rn(acc[mt][nt][2] + b0);
                c1[t + 8] = __float2half_rn(acc[mt][nt][3] + b1);
            }
        }
    } else {
        // fp16 output C[m,n]
        __half* Ch = (__half*)C;
#pragma unroll
        for (int nt = 0; nt < 4; nt++) {
            const int n  = n0 + wn + nt * 8 + 2 * t4;
            const float b0 = __ldg(bias + n);
            const float b1 = __ldg(bias + n + 1);
#pragma unroll
            for (int mt = 0; mt < 4; mt++) {
                const int mrow = m0 + wm + mt * 16 + g;
                *(__half2*)&Ch[(size_t)mrow * EE + n] =
                    __floats2half2_rn(acc[mt][nt][0] + b0, acc[mt][nt][1] + b1);
                *(__half2*)&Ch[(size_t)(mrow + 8) * EE + n] =
                    __floats2half2_rn(acc[mt][nt][2] + b0, acc[mt][nt][3] + b1);
            }
        }
    }
}

// ===================== radix-4 4096-pt FFT, stages fully unrolled =====================
__device__ __forceinline__ void fft4096_r4(float2* s, int tid) {
#pragma unroll
    for (int st = 0; st < 6; st++) {
        const int l2m = 2 * st;
        const int m   = 1 << l2m;
#pragma unroll
        for (int u = 0; u < 2; u++) {
            int bi   = tid + (u << 9);
            int j    = bi & (m - 1);
            int base = ((bi >> l2m) << (l2m + 2)) | j;
            float2 x0 = s[base];
            float2 x1 = s[base + m];
            float2 x2 = s[base + 2 * m];
            float2 x3 = s[base + 3 * m];
            int e = j << (10 - l2m);
            float2 w1 = g_tw[e];
            float2 w2 = g_tw[2 * e];
            float2 w3 = cmulf(w1, w2);
            float2 t1 = cmulf(x1, w1);
            float2 t2 = cmulf(x2, w2);
            float2 t3 = cmulf(x3, w3);
            float2 a = make_float2(x0.x + t2.x, x0.y + t2.y);
            float2 b = make_float2(x0.x - t2.x, x0.y - t2.y);
            float2 c = make_float2(t1.x + t3.x, t1.y + t3.y);
            float2 d = make_float2(t1.x - t3.x, t1.y - t3.y);
            s[base]         = make_float2(a.x + c.x, a.y + c.y);
            s[base + 2 * m] = make_float2(a.x - c.x, a.y - c.y);
            s[base + m]     = make_float2(b.x + d.y, b.y - d.x);
            s[base + 3 * m] = make_float2(b.x - d.y, b.y + d.x);
        }
        __syncthreads();
    }
}

__device__ __forceinline__ int digrev4(int i) {
    int r = __brev(i) >> 20;
    return ((r & 0x555) << 1) | ((r & 0xAAA) >> 1);
}

// ===================== forward correlation spectrum (q + i*k pack trick) ==========
__global__ void __launch_bounds__(512) corrfft_kernel() {
    __shared__ float2 s[4096];
    const int tid = threadIdx.x;
    const int b   = blockIdx.x >> 7;
    const int e0  = (blockIdx.x & 127) * 8;

    float2 psum[8];
#pragma unroll
    for (int r = 0; r < 8; r++) psum[r] = make_float2(0.f, 0.f);

    for (int c = 0; c < 8; c++) {
        const int ch = e0 + c;
        const __half* q = g_Qth + ((size_t)(b * 1024 + ch)) * 4096;
        const __half* k = g_Kth + ((size_t)(b * 1024 + ch)) * 4096;
        __syncthreads();
        for (int i = tid; i < 4096; i += 512)
            s[digrev4(i)] = make_float2(__half2float(q[i]), __half2float(k[i]));
        __syncthreads();
        fft4096_r4(s, tid);
#pragma unroll
        for (int r = 0; r < 8; r++) {
            int f = tid + (r << 9);
            float2 A  = s[f];
            float2 Bc = s[(4096 - f) & 4095];
            float qr = 0.5f * (A.x + Bc.x);
            float qi = 0.5f * (A.y - Bc.y);
            float kr = 0.5f * (A.y + Bc.y);
            float ki = 0.5f * (Bc.x - A.x);
            psum[r].x += qr * kr + qi * ki;
            psum[r].y += qi * kr - qr * ki;
        }
    }

    float2* spec = g_spec + b * 4096;
#pragma unroll
    for (int r = 0; r < 8; r++) {
        int f = tid + (r << 9);
        atomicAdd(&spec[f].x, psum[r].x);
        atomicAdd(&spec[f].y, psum[r].y);
    }
}

// ===================== fused inverse FFT + top-24 =====================
__global__ void __launch_bounds__(512) ifft_topk_kernel() {
    __shared__ float2 s[4096];
    __shared__ float rv[16];
    __shared__ int   ri[16];
    __shared__ float bwv;
    __shared__ int   bwi;
    const int b    = blockIdx.x;
    const int tid  = threadIdx.x;
    const int wrp  = tid >> 5;
    const int lane = tid & 31;

    for (int i = tid; i < 4096; i += 512) {
        float2 v = g_spec[b * 4096 + i];
        s[digrev4(i)] = make_float2(v.x, -v.y);   // conj -> fwd fft -> Re = Re(ifft)*N
    }
    __syncthreads();
    fft4096_r4(s, tid);

    const float scale = 1.0f / ((float)TT * (float)EE);
    float val[8];
    int   idx[8];
#pragma unroll
    for (int r = 0; r < 8; r++) {
        int f  = tid + (r << 9);
        val[r] = s[f].x * scale;
        idx[r] = f;
    }

    for (int kk = 0; kk < KTOP; kk++) {
        float best = -3.4e38f;
        int   bi   = 0x7fffffff;
#pragma unroll
        for (int r = 0; r < 8; r++) {
            float v = val[r];
            if (v > best || (v == best && idx[r] < bi)) { best = v; bi = idx[r]; }
        }
#pragma unroll
        for (int off = 16; off > 0; off >>= 1) {
            float ov = __shfl_down_sync(0xFFFFFFFF, best, off);
            int   oi = __shfl_down_sync(0xFFFFFFFF, bi, off);
            if (ov > best || (ov == best && oi < bi)) { best = ov; bi = oi; }
        }
        if (lane == 0) { rv[wrp] = best; ri[wrp] = bi; }
        __syncthreads();
        if (wrp == 0) {
            float wv = (lane < 16) ? rv[lane] : -3.4e38f;
            int   wi = (lane < 16) ? ri[lane] : 0x7fffffff;
#pragma unroll
            for (int off = 8; off > 0; off >>= 1) {
                float ov = __shfl_down_sync(0xFFFFFFFF, wv, off);
                int   oi = __shfl_down_sync(0xFFFFFFFF, wi, off);
                if (ov > wv || (ov == wv && oi < wi)) { wv = ov; wi = oi; }
            }
            if (lane == 0) {
                g_topv[b * KTOP + kk] = wv;
                g_topi[b * KTOP + kk] = wi;
                bwv = wv; bwi = wi;
            }
        }
        __syncthreads();
        const int kill = bwi;
#pragma unroll
        for (int r = 0; r < 8; r++)
            if (idx[r] == kill) val[r] = -3.4e38f;
    }
}

// agg[b,t,e] = sum_k w[g,k] * V[b,(t+d[g,k])%T,e],  g = (e/64)%8; V fp16 -> agg fp16
__global__ void __launch_bounds__(128) agg_kernel() {
    __shared__ float ws[8 * KTOP];
    __shared__ int   ds[8 * KTOP];
    const int tid = threadIdx.x;
    for (int i = tid; i < 8 * KTOP; i += 128) { ws[i] = g_topv[i]; ds[i] = g_topi[i]; }
    __syncthreads();

    const int bt = blockIdx.x;
    const int b  = bt >> 12;
    const int t  = bt & 4095;
    const int e8 = tid << 3;
    const int gg = (e8 >> 6) & 7;

    const __half* Vb = g_Vh + (size_t)b * TT * EE;
    float acc[8];
#pragma unroll
    for (int i = 0; i < 8; i++) acc[i] = 0.f;

#pragma unroll
    for (int kk = 0; kk < KTOP; kk++) {
        int   tk = (t + ds[gg * KTOP + kk]) & 4095;
        float w  = ws[gg * KTOP + kk];
        uint4 raw = *(const uint4*)&Vb[(size_t)tk * EE + e8];
        __half2 h0, h1, h2, h3;
        *(uint32_t*)&h0 = raw.x; *(uint32_t*)&h1 = raw.y;
        *(uint32_t*)&h2 = raw.z; *(uint32_t*)&h3 = raw.w;
        float2 f0 = __half22float2(h0), f1 = __half22float2(h1);
        float2 f2 = __half22float2(h2), f3 = __half22float2(h3);
        acc[0] += w * f0.x; acc[1] += w * f0.y;
        acc[2] += w * f1.x; acc[3] += w * f1.y;
        acc[4] += w * f2.x; acc[5] += w * f2.y;
        acc[6] += w * f3.x; acc[7] += w * f3.y;
    }

    __half2 p0 = __floats2half2_rn(acc[0], acc[1]);
    __half2 p1 = __floats2half2_rn(acc[2], acc[3]);
    __half2 p2 = __floats2half2_rn(acc[4], acc[5]);
    __half2 p3 = __floats2half2_rn(acc[6], acc[7]);
    uint4 outv = make_uint4(*(uint32_t*)&p0, *(uint32_t*)&p1,
                            *(uint32_t*)&p2, *(uint32_t*)&p3);
    *(uint4*)(g_aggh + (size_t)bt * EE + e8) = outv;
}

// ===================== launch =====================
extern "C" void kernel_launch(void* const* d_in, const int* in_sizes, int n_in,
                              void* d_out, int out_size) {
    (void)in_sizes; (void)n_in; (void)out_size;
    const float* hs = (const float*)d_in[0];
    const float* Wq = (const float*)d_in[1];
    const float* bq = (const float*)d_in[2];
    const float* Wk = (const float*)d_in[3];
    const float* bk = (const float*)d_in[4];
    const float* Wv = (const float*)d_in[5];
    const float* bv = (const float*)d_in[6];
    const float* Wo = (const float*)d_in[7];
    const float* bo = (const float*)d_in[8];
    float* out = (float*)d_out;

    cudaFuncSetAttribute(hgemm_kernel,
                         cudaFuncAttributeMaxDynamicSharedMemorySize, GEMM_SMEM);

    void *pXh, *pWth, *pQth, *pKth, *pVh, *pAggh;
    cudaGetSymbolAddress(&pXh,   g_Xh);
    cudaGetSymbolAddress(&pWth,  g_Wth);
    cudaGetSymbolAddress(&pQth,  g_Qth);
    cudaGetSymbolAddress(&pKth,  g_Kth);
    cudaGetSymbolAddress(&pVh,   g_Vh);
    cudaGetSymbolAddress(&pAggh, g_aggh);

    const __half* Wth = (const __half*)pWth;

    prep_kernel<<<(BB * TT * EE / 4) / 256, 256>>>(hs);
    transpose4_kernel<<<dim3(EE / 32, EE / 32, 4), dim3(32, 8)>>>(Wq, Wk, Wv, Wo);

    const dim3 ggrid(EE / BN, (BB * TT) / BM);

    hgemm_kernel<<<ggrid, 256, GEMM_SMEM>>>((const __half*)pXh, Wth + 0 * EE * EE, bq, (float*)pQth, 1);
    hgemm_kernel<<<ggrid, 256, GEMM_SMEM>>>((const __half*)pXh, Wth + 1 * EE * EE, bk, (float*)pKth, 1);
    hgemm_kernel<<<ggrid, 256, GEMM_SMEM>>>((const __half*)pXh, Wth + 2 * EE * EE, bv, (float*)pVh,  2);

    corrfft_kernel<<<BB * 128, 512>>>();
    ifft_topk_kernel<<<BB, 512>>>();
    agg_kernel<<<BB * TT, 128>>>();

    hgemm_kernel<<<ggrid, 256, GEMM_SMEM>>>((const __half*)pAggh, Wth + 3 * EE * EE, bo, out, 0);
}